// round 6
// baseline (speedup 1.0000x reference)
#include <cuda_runtime.h>
#include <cuda_bf16.h>
#include <cuda_fp16.h>

#define BB 64
#define SS 512
#define EE 512
#define AA 256
#define HP 256
#define PP 128
#define DD 1024
#define MM 128
#define TT 800
#define G3 3072
#define NB 128
#define TPB 1024
#define KT2 2688
#define NKT 104
#define NCH 26

// ---------------- static scratch ----------------
__device__ __align__(128) __half g_epH[BB*SS*AA];
__device__ __align__(128) __half g_encH[BB*SS*EE];
__device__ __align__(128) float g_prev[TT*BB*MM];
__device__ __align__(128) float g_ph  [TT*BB*HP];
__device__ __align__(128) float g_pre [TT*BB*PP];
__device__ __align__(128) float g_h   [BB*DD];
__device__ __align__(128) float g_sc  [BB*SS];
__device__ __align__(128) float g_dpp [BB*NB*AA];
__device__ __align__(128) __nv_bfloat16 g_Ah[BB*KT2];
__device__ __align__(128) __nv_bfloat16 g_Al[BB*KT2];
__device__ __align__(128) uint2 g_Wf[(size_t)NB*NKT*3*2*32];
__device__ __align__(128) float g_Hb  [(size_t)TT*BB*DD];
__device__ __align__(128) float g_Cb  [(size_t)TT*BB*EE];
__device__ __align__(128) volatile unsigned g_flags[NB*32];   // 128B-padded arrival flags
__device__ volatile unsigned g_rel;

__device__ __forceinline__ float fsig(float x){
    float e = __expf(-x);
    return __fdividef(1.f, 1.f + e);
}
__device__ __forceinline__ float ftanh(float x){
    x = fminf(fmaxf(x, -15.f), 15.f);
    float e = __expf(2.f*x);
    return __fdividef(e - 1.f, e + 1.f);
}
__device__ __forceinline__ float tanh_mufu(float x){
    float y; asm("tanh.approx.f32 %0, %1;" : "=f"(y) : "f"(x)); return y;
}

// flag-array grid barrier: parallel arrivals, single release word
__device__ __forceinline__ void gsync(unsigned &gen){
    gen++;
    __syncthreads();
    const int tid = threadIdx.x;
    if (blockIdx.x == 0){
        if (tid == 0){ __threadfence(); g_flags[0] = gen; }
        if (tid > 0 && tid < NB){
            while (g_flags[tid*32] < gen) {}
        }
        __syncthreads();
        if (tid == 0){ __threadfence(); g_rel = gen; }
    } else {
        if (tid == 0){
            __threadfence();
            g_flags[blockIdx.x*32] = gen;
            while (g_rel < gen) {}
            __threadfence();
        }
    }
    __syncthreads();
}

#define MMA(D0,D1,D2,D3,A0,A1,A2,A3,B0,B1) \
    asm volatile("mma.sync.aligned.m16n8k16.row.col.f32.bf16.bf16.f32 " \
        "{%0,%1,%2,%3},{%4,%5,%6,%7},{%8,%9},{%0,%1,%2,%3};" \
        : "+f"(D0),"+f"(D1),"+f"(D2),"+f"(D3) \
        : "r"(A0),"r"(A1),"r"(A2),"r"(A3),"r"(B0),"r"(B1))

// ---------------- generic tiled SGEMM (pre/epilogue only) ----------------
#define BKK 16
__global__ void sgemm(const float* __restrict__ A, const float* __restrict__ B,
                      const float* __restrict__ bias, float* __restrict__ C,
                      int M, int N, int K, int flags, int Bdim, int Tdim)
{
    __shared__ float As[BKK][64];
    __shared__ float Bs[BKK][64];
    const int n0 = blockIdx.x * 64;
    const int m0 = blockIdx.y * 64;
    const int tid = threadIdx.x;
    const int tx = tid & 15;
    const int ty = tid >> 4;
    float acc[4][4] = {};
    const int arow  = tid >> 2;
    const int acol4 = (tid & 3) * 4;
    const int brow  = tid >> 4;
    const int bcol4 = (tid & 15) * 4;

    for (int k = 0; k < K; k += BKK) {
        float4 av = *(const float4*)(A + (size_t)(m0 + arow) * K + k + acol4);
        As[acol4+0][arow] = av.x;
        As[acol4+1][arow] = av.y;
        As[acol4+2][arow] = av.z;
        As[acol4+3][arow] = av.w;
        float4 bvv = *(const float4*)(B + (size_t)(k + brow) * N + n0 + bcol4);
        *(float4*)(&Bs[brow][bcol4]) = bvv;
        __syncthreads();
        #pragma unroll
        for (int kk = 0; kk < BKK; kk++) {
            float4 a4 = *(const float4*)(&As[kk][ty*4]);
            float4 b4 = *(const float4*)(&Bs[kk][tx*4]);
            acc[0][0] += a4.x*b4.x; acc[0][1] += a4.x*b4.y; acc[0][2] += a4.x*b4.z; acc[0][3] += a4.x*b4.w;
            acc[1][0] += a4.y*b4.x; acc[1][1] += a4.y*b4.y; acc[1][2] += a4.y*b4.z; acc[1][3] += a4.y*b4.w;
            acc[2][0] += a4.z*b4.x; acc[2][1] += a4.z*b4.y; acc[2][2] += a4.z*b4.z; acc[2][3] += a4.z*b4.w;
            acc[3][0] += a4.w*b4.x; acc[3][1] += a4.w*b4.y; acc[3][2] += a4.w*b4.z; acc[3][3] += a4.w*b4.w;
        }
        __syncthreads();
    }
    #pragma unroll
    for (int i = 0; i < 4; i++) {
        const int m = m0 + ty*4 + i;
        #pragma unroll
        for (int j = 0; j < 4; j++) {
            const int n = n0 + tx*4 + j;
            float val = acc[i][j];
            if (bias) val += bias[n];
            if (flags & 1) val = fmaxf(val, 0.f);
            size_t idx;
            if (Bdim > 0) {
                const int bq = m % Bdim, tq = m / Bdim;
                idx = ((size_t)bq * Tdim + tq) * N + n;
            } else {
                idx = (size_t)m * N + n;
            }
            if (flags & 4)      ((__half*)C)[idx] = __float2half_rn(val);
            else if (flags & 2) C[idx] += val;
            else                C[idx] = val;
        }
    }
}

__global__ void k_init(){
    int i = blockIdx.x*256 + threadIdx.x;
    if (i < BB*NB*AA) g_dpp[i] = 0.f;
    if (i < BB*KT2){ g_Ah[i] = __float2bfloat16(0.f); g_Al[i] = __float2bfloat16(0.f); }
    if (i < BB*DD) g_h[i] = 0.f;
}

__global__ void k_prev(const float* __restrict__ tm){
    int i = blockIdx.x*256 + threadIdx.x;
    if (i >= TT*BB*MM) return;
    int m  = i & (MM-1);
    int tb = i >> 7;
    int b  = tb & (BB-1);
    int t  = tb >> 6;
    g_prev[i] = (t == 0) ? 0.f : tm[((size_t)b*TT + (t-1))*MM + m];
}

__global__ void k_convE(const float* __restrict__ enc){
    int i = blockIdx.x*256 + threadIdx.x;
    if (i < BB*SS*EE) g_encH[i] = __float2half_rn(enc[i]);
}

__global__ void k_pack(const float* __restrict__ Wih, const float* __restrict__ Whh){
    int id = blockIdx.x*256 + threadIdx.x;
    const int TOTW = NB*NKT*3*32;
    if (id >= TOTW) return;
    int lane = id & 31; int r = id >> 5;
    int nt = r % 3; r /= 3;
    int kt = r % NKT; int blk = r / NKT;
    int g = lane >> 2, tig = lane & 3;
    int n = nt*DD + blk*8 + g;
    int k0 = kt*16;
    int kk[4] = {k0+2*tig, k0+2*tig+1, k0+8+2*tig, k0+9+2*tig};
    unsigned hh[4], ll[4];
    #pragma unroll
    for (int i=0;i<4;i++){
        int k = kk[i];
        float w = (k < PP+EE) ? Wih[(size_t)k*G3 + n] : Whh[(size_t)(k-(PP+EE))*G3 + n];
        __nv_bfloat16 hb = __float2bfloat16(w);
        __nv_bfloat16 lb = __float2bfloat16(w - __bfloat162float(hb));
        hh[i] = *(unsigned short*)&hb;
        ll[i] = *(unsigned short*)&lb;
    }
    size_t base = ((((size_t)blk*NKT + kt)*3 + nt)*2)*32 + lane;
    g_Wf[base]      = make_uint2((hh[1]<<16)|hh[0], (hh[3]<<16)|hh[2]);
    g_Wf[base + 32] = make_uint2((ll[1]<<16)|ll[0], (ll[3]<<16)|ll[2]);
}

__global__ void k_stop(const float* __restrict__ Ws, const float* __restrict__ bs,
                       float* __restrict__ dout){
    const int w = (blockIdx.x*blockDim.x + threadIdx.x) >> 5;
    const int lane = threadIdx.x & 31;
    if (w >= TT*BB) return;
    const float* hrow = g_Hb + (size_t)w*DD;
    const float* crow = g_Cb + (size_t)w*EE;
    float acc = 0.f;
    for (int k = lane; k < DD; k += 32) acc += hrow[k]*Ws[k];
    for (int k = lane; k < EE; k += 32) acc += crow[k]*Ws[DD+k];
    #pragma unroll
    for (int o = 16; o > 0; o >>= 1) acc += __shfl_down_sync(0xffffffffu, acc, o);
    if (lane == 0){
        const int tq = w / BB, bq = w % BB;
        dout[(size_t)BB*TT*MM + (size_t)bq*TT + tq] = acc + bs[0];
    }
}

// one phase-C iteration: MMAs on current slot/frags, prefetch next
#define CIT(i, BHc, BLc, BHn, BLn) { \
    const int inext = (i) + 1; \
    uint4 nvh, nvl; \
    const bool stg = inext < 13; \
    if (stg){ \
        const int cs = half*13 + inext; \
        const int idx4 = (cs < 10) ? cs*8 : 80 + (cs-10)*8 + par*128; \
        nvh = ((const uint4*)g_Ah)[srow*336 + idx4 + sc4]; \
        nvl = ((const uint4*)g_Al)[srow*336 + idx4 + sc4]; \
        if (mma_on){ \
            size_t wb = ((((size_t)blk*NKT + (size_t)(cbeg+inext)*4)*3 + nt)*2)*32 + lane; \
            _Pragma("unroll") \
            for (int kl=0; kl<4; kl++){ \
                BHn[kl] = g_Wf[wb + (size_t)kl*192]; \
                BLn[kl] = g_Wf[wb + (size_t)kl*192 + 32]; \
            } \
        } \
    } \
    if (mma_on){ \
        const unsigned* Ah32 = smu + (((i)&1)*2 + ks)*4608; \
        const unsigned* Al32 = Ah32 + 2304; \
        const bool useH = (nt == 2) && ((cbeg+(i)) >= 10); \
        _Pragma("unroll") \
        for (int kl=0; kl<4; kl++){ \
            int r0 = (m0+g)*36 + kl*8 + tig; \
            unsigned a0 = Ah32[r0],   a1 = Ah32[r0+288]; \
            unsigned a2 = Ah32[r0+4], a3 = Ah32[r0+292]; \
            unsigned l0 = Al32[r0],   l1 = Al32[r0+288]; \
            unsigned l2 = Al32[r0+4], l3 = Al32[r0+292]; \
            if (useH){ \
                MMA(aH0,aH1,aH2,aH3, a0,a1,a2,a3, BHc[kl].x, BHc[kl].y); \
                MMA(aH0,aH1,aH2,aH3, a0,a1,a2,a3, BLc[kl].x, BLc[kl].y); \
                MMA(aH0,aH1,aH2,aH3, l0,l1,l2,l3, BHc[kl].x, BHc[kl].y); \
            } else { \
                MMA(aX0,aX1,aX2,aX3, a0,a1,a2,a3, BHc[kl].x, BHc[kl].y); \
                MMA(aX0,aX1,aX2,aX3, a0,a1,a2,a3, BLc[kl].x, BLc[kl].y); \
                MMA(aX0,aX1,aX2,aX3, l0,l1,l2,l3, BHc[kl].x, BHc[kl].y); \
            } \
        } \
    } \
    if (stg){ \
        unsigned boff = ((inext&1)*2 + half)*4608; \
        ((uint4*)(smu + boff))[srow*9 + sc4] = nvh; \
        ((uint4*)(smu + boff + 2304))[srow*9 + sc4] = nvl; \
    } \
    __syncthreads(); \
}

// ================= persistent decode kernel =================
__global__ void __launch_bounds__(TPB, 1)
decode(const float* __restrict__ Wd,  const float* __restrict__ bd,
       const float* __restrict__ v,   const float* __restrict__ bv,
       const float* __restrict__ bih, const float* __restrict__ bhh,
       float* __restrict__ out)
{
    extern __shared__ float smf[];
    unsigned* smu = (unsigned*)smf;
    const int blk = blockIdx.x, tid = threadIdx.x;
    const int lane = tid & 31, wq = tid >> 5;
    unsigned gen = g_rel;

    for (int t = 0; t < TT; t++){
        const int par = t & 1;
        // ---------- A: dp partial-sum + attention scores ----------
        {
            const int b = blk >> 1, sh = blk & 1;
            float* dps = smf; float* vs = smf + 256; float* part = smf + 512;
            {
                const int a = tid & 255, jh = tid >> 8;
                const float* pp = g_dpp + ((size_t)b*NB + jh*32)*AA + a;
                float s = 0.f;
                #pragma unroll 8
                for (int j = 0; j < 32; j++) s += pp[(size_t)j*AA];
                part[tid] = s;
            }
            __syncthreads();
            if (tid < 256){
                dps[tid] = part[tid] + part[256+tid] + part[512+tid] + part[768+tid] + bd[tid];
                vs[tid] = v[tid];
            }
            __syncthreads();
            const int sl = tid >> 2, ah = tid & 3;
            const int s = sh*256 + sl;
            const uint4* ep4 = (const uint4*)(g_epH + ((size_t)(b*SS + s))*AA + ah*64);
            const float* dp2 = dps + ah*64;
            const float* v2  = vs  + ah*64;
            float acc = 0.f;
            #pragma unroll
            for (int q = 0; q < 8; q++){
                uint4 u = ep4[q];
                float2 f0 = __half22float2(*(__half2*)&u.x);
                float2 f1 = __half22float2(*(__half2*)&u.y);
                float2 f2 = __half22float2(*(__half2*)&u.z);
                float2 f3 = __half22float2(*(__half2*)&u.w);
                const int i0 = q*8;
                acc += v2[i0+0]*tanh_mufu(f0.x + dp2[i0+0]);
                acc += v2[i0+1]*tanh_mufu(f0.y + dp2[i0+1]);
                acc += v2[i0+2]*tanh_mufu(f1.x + dp2[i0+2]);
                acc += v2[i0+3]*tanh_mufu(f1.y + dp2[i0+3]);
                acc += v2[i0+4]*tanh_mufu(f2.x + dp2[i0+4]);
                acc += v2[i0+5]*tanh_mufu(f2.y + dp2[i0+5]);
                acc += v2[i0+6]*tanh_mufu(f3.x + dp2[i0+6]);
                acc += v2[i0+7]*tanh_mufu(f3.y + dp2[i0+7]);
            }
            acc += __shfl_xor_sync(0xffffffffu, acc, 1);
            acc += __shfl_xor_sync(0xffffffffu, acc, 2);
            if (ah == 0) g_sc[b*SS + s] = acc + bv[0];
            __syncthreads();
        }
        gsync(gen);
        // ---------- B: softmax + context + pre/ctx staging ----------
        {
            const int b = blk >> 1, eh = blk & 1;
            float* aw = smf; float* red = smf + 512; float* sm2 = smf + 576;
            float sc = -1e30f, ev = 0.f;
            if (tid < 512) sc = g_sc[b*SS + tid];
            float mx = sc;
            #pragma unroll
            for (int o = 16; o; o >>= 1) mx = fmaxf(mx, __shfl_xor_sync(0xffffffffu, mx, o));
            if (lane == 0) red[wq] = mx;
            __syncthreads();
            if (tid < 32){
                float mm = (tid < 16) ? red[tid] : -1e30f;
                #pragma unroll
                for (int o = 8; o; o >>= 1) mm = fmaxf(mm, __shfl_xor_sync(0xffffffffu, mm, o));
                if (tid == 0) red[33] = mm;
            }
            __syncthreads();
            mx = red[33];
            if (tid < 512) ev = __expf(sc - mx);
            float ss = ev;
            #pragma unroll
            for (int o = 16; o; o >>= 1) ss += __shfl_xor_sync(0xffffffffu, ss, o);
            if (lane == 0) red[wq] = ss;
            __syncthreads();
            if (tid < 32){
                float s2 = (tid < 16) ? red[tid] : 0.f;
                #pragma unroll
                for (int o = 8; o; o >>= 1) s2 += __shfl_xor_sync(0xffffffffu, s2, o);
                if (tid == 0) red[34] = s2;
            }
            __syncthreads();
            const float inv = __fdividef(1.f, red[34]);
            if (tid < 512){
                float a = ev * inv;
                aw[tid] = a;
                if (eh == 0)
                    out[(size_t)BB*TT*MM + (size_t)BB*TT + ((size_t)b*TT + t)*SS + tid] = a;
            } else if (tid < 640 && eh == 0){
                int m = tid - 512;
                float pv = g_pre[((size_t)t*BB + b)*PP + m];
                __nv_bfloat16 hb = __float2bfloat16(pv);
                g_Ah[b*KT2 + m] = hb;
                g_Al[b*KT2 + m] = __float2bfloat16(pv - __bfloat162float(hb));
            }
            __syncthreads();
            const int el = tid & 127, sq = tid >> 7;
            const __half2* eb = (const __half2*)(g_encH + ((size_t)(b*SS + sq*64))*EE + eh*256) + el;
            const float* awq = aw + sq*64;
            float c0 = 0.f, c1 = 0.f;
            #pragma unroll 8
            for (int s2 = 0; s2 < 64; s2++){
                float2 e = __half22float2(eb[(size_t)s2*(EE/2)]);
                float a2 = awq[s2];
                c0 += a2*e.x; c1 += a2*e.y;
            }
            sm2[sq*256 + el*2]     = c0;
            sm2[sq*256 + el*2 + 1] = c1;
            __syncthreads();
            if (tid < 256){
                float cc = 0.f;
                #pragma unroll
                for (int q = 0; q < 8; q++) cc += sm2[q*256 + tid];
                const int e2 = eh*256 + tid;
                g_Cb[((size_t)t*BB + b)*EE + e2] = cc;
                __nv_bfloat16 hb = __float2bfloat16(cc);
                g_Ah[b*KT2 + PP + e2] = hb;
                g_Al[b*KT2 + PP + e2] = __float2bfloat16(cc - __bfloat162float(hb));
            }
            __syncthreads();
        }
        gsync(gen);
        // ---------- C: gates mma GEMM (k-split x2) + GRU + dp partials ----------
        {
            const bool mma_on = (wq < 24);
            const int ks = wq / 12, id = wq % 12;
            const int nt = id >> 2, m0 = (id & 3) * 16;
            const int cbeg = ks * 13;
            const int g = lane >> 2, tig = lane & 3;
            const int half = tid >> 9;
            const int srow = (tid >> 3) & 63, sc4 = tid & 7;
            float aX0=0,aX1=0,aX2=0,aX3=0, aH0=0,aH1=0,aH2=0,aH3=0;
            uint2 bh0[4], bl0[4], bh1[4], bl1[4];
            {
                const int cs = half*13;
                const int idx4 = (cs < 10) ? cs*8 : 80 + (cs-10)*8 + par*128;
                uint4 vh = ((const uint4*)g_Ah)[srow*336 + idx4 + sc4];
                uint4 vl = ((const uint4*)g_Al)[srow*336 + idx4 + sc4];
                ((uint4*)(smu + half*4608))[srow*9 + sc4] = vh;
                ((uint4*)(smu + half*4608 + 2304))[srow*9 + sc4] = vl;
                if (mma_on){
                    size_t wb = ((((size_t)blk*NKT + (size_t)cbeg*4)*3 + nt)*2)*32 + lane;
                    #pragma unroll
                    for (int kl=0; kl<4; kl++){
                        bh0[kl] = g_Wf[wb + (size_t)kl*192];
                        bl0[kl] = g_Wf[wb + (size_t)kl*192 + 32];
                    }
                }
            }
            __syncthreads();
            CIT(0,  bh0, bl0, bh1, bl1)
            CIT(1,  bh1, bl1, bh0, bl0)
            CIT(2,  bh0, bl0, bh1, bl1)
            CIT(3,  bh1, bl1, bh0, bl0)
            CIT(4,  bh0, bl0, bh1, bl1)
            CIT(5,  bh1, bl1, bh0, bl0)
            CIT(6,  bh0, bl0, bh1, bl1)
            CIT(7,  bh1, bl1, bh0, bl0)
            CIT(8,  bh0, bl0, bh1, bl1)
            CIT(9,  bh1, bl1, bh0, bl0)
            CIT(10, bh0, bl0, bh1, bl1)
            CIT(11, bh1, bl1, bh0, bl0)
            CIT(12, bh0, bl0, bh1, bl1)
            // gate frags -> smem planes [2ks][4][64][8]
            float* sg = smf;
            if (mma_on){
                float* pl = sg + ks*2048 + nt*512;
                int rr = (m0+g)*8 + 2*tig;
                pl[rr]=aX0; pl[rr+1]=aX1; pl[rr+64]=aX2; pl[rr+65]=aX3;
                if (nt == 2){
                    float* p3 = sg + ks*2048 + 3*512;
                    p3[rr]=aH0; p3[rr+1]=aH1; p3[rr+64]=aH2; p3[rr+65]=aH3;
                }
            }
            float* Wds = smf + 4096; float* hs = smf + 6144;
            if (tid < 512){
                const int row = tid >> 6, c4 = (tid & 63)*4;
                *(float4*)(Wds + row*256 + c4) = *(const float4*)(Wd + (size_t)(blk*8+row)*AA + c4);
            }
            __syncthreads();
            if (tid < 512){
                const int b = tid >> 3, dl = tid & 7, d = blk*8 + dl;
                const int ix = b*8 + dl;
                float gr  = sg[ix]        + sg[2048+ix]        + bih[d] + bhh[d];
                float gz  = sg[512 + ix]  + sg[2048+512+ix]    + bih[DD+d] + bhh[DD+d];
                float gin = sg[1024 + ix] + sg[2048+1024+ix]   + bih[2*DD+d];
                float ghn = sg[1536 + ix] + sg[2048+1536+ix]   + bhh[2*DD+d];
                float r = fsig(gr), z = fsig(gz);
                float n = ftanh(gin + r*ghn);
                float h = g_h[b*DD + d];
                float hn = (1.f - z)*n + z*h;
                g_h[b*DD + d] = hn;
                g_Hb[((size_t)t*BB + b)*DD + d] = hn;
                __nv_bfloat16 hb = __float2bfloat16(hn);
                const int hoff = PP+EE + ((t+1)&1)*DD + d;
                g_Ah[b*KT2 + hoff] = hb;
                g_Al[b*KT2 + hoff] = __float2bfloat16(hn - __bfloat162float(hb));
                hs[b*8 + dl] = hn;
            }
            __syncthreads();
            {
                const int bg = tid >> 5, ag = lane;
                const int b2 = bg*2, a8 = ag*8;
                float acc[2][8] = {};
                #pragma unroll
                for (int kk = 0; kk < 8; kk++){
                    const float4 w0 = *(const float4*)(Wds + kk*256 + a8);
                    const float4 w1 = *(const float4*)(Wds + kk*256 + a8 + 4);
                    #pragma unroll
                    for (int i = 0; i < 2; i++){
                        const float h = hs[(b2+i)*8 + kk];
                        acc[i][0]+=h*w0.x; acc[i][1]+=h*w0.y; acc[i][2]+=h*w0.z; acc[i][3]+=h*w0.w;
                        acc[i][4]+=h*w1.x; acc[i][5]+=h*w1.y; acc[i][6]+=h*w1.z; acc[i][7]+=h*w1.w;
                    }
                }
                #pragma unroll
                for (int i = 0; i < 2; i++){
                    float* o = g_dpp + ((size_t)(b2+i)*NB + blk)*AA + a8;
                    *(float4*)(o)   = make_float4(acc[i][0],acc[i][1],acc[i][2],acc[i][3]);
                    *(float4*)(o+4) = make_float4(acc[i][4],acc[i][5],acc[i][6],acc[i][7]);
                }
            }
        }
        gsync(gen);
    }
}

// ---------------- host ----------------
extern "C" void kernel_launch(void* const* d_in, const int* in_sizes, int n_in,
                              void* d_out, int out_size){
    const float* enc = (const float*)d_in[0];
    const float* tm  = (const float*)d_in[1];
    const float* We  = (const float*)d_in[2];
    const float* be  = (const float*)d_in[3];
    const float* Wd  = (const float*)d_in[4];
    const float* bd  = (const float*)d_in[5];
    const float* v   = (const float*)d_in[6];
    const float* bv  = (const float*)d_in[7];
    const float* W1  = (const float*)d_in[8];
    const float* b1  = (const float*)d_in[9];
    const float* W2  = (const float*)d_in[10];
    const float* b2  = (const float*)d_in[11];
    const float* Wih = (const float*)d_in[12];
    const float* bih = (const float*)d_in[13];
    const float* Whh = (const float*)d_in[14];
    const float* bhh = (const float*)d_in[15];
    const float* Wo  = (const float*)d_in[16];
    const float* bo  = (const float*)d_in[17];
    const float* Ws  = (const float*)d_in[18];
    const float* bs  = (const float*)d_in[19];
    float* out = (float*)d_out;

    float *p_prev, *p_ph, *p_pre, *p_Hb, *p_Cb; __half *p_epH;
    cudaGetSymbolAddress((void**)&p_epH,  g_epH);
    cudaGetSymbolAddress((void**)&p_prev, g_prev);
    cudaGetSymbolAddress((void**)&p_ph,   g_ph);
    cudaGetSymbolAddress((void**)&p_pre,  g_pre);
    cudaGetSymbolAddress((void**)&p_Hb,   g_Hb);
    cudaGetSymbolAddress((void**)&p_Cb,   g_Cb);

    static bool attr_set = false;
    if (!attr_set){
        cudaFuncSetAttribute(decode, cudaFuncAttributeMaxDynamicSharedMemorySize, 73728);
        attr_set = true;
    }

    // precompute
    k_init<<<(BB*NB*AA + 255)/256, 256>>>();
    k_prev<<<(TT*BB*MM + 255)/256, 256>>>(tm);
    k_convE<<<(BB*SS*EE + 255)/256, 256>>>(enc);
    k_pack<<<(NB*NKT*3*32 + 255)/256, 256>>>(Wih, Whh);
    sgemm<<<dim3(HP/64, (TT*BB)/64), 256>>>(p_prev, W1, b1, p_ph,  TT*BB, HP, MM, 1, 0, 0);
    sgemm<<<dim3(PP/64, (TT*BB)/64), 256>>>(p_ph,   W2, b2, p_pre, TT*BB, PP, HP, 1, 0, 0);
    sgemm<<<dim3(AA/64, (BB*SS)/64), 256>>>(enc,    We, be, (float*)p_epH, BB*SS, AA, EE, 4, 0, 0);

    // sequential decode: one persistent kernel
    decode<<<NB, TPB, 73728>>>(Wd, bd, v, bv, bih, bhh, out);

    // output heads
    sgemm<<<dim3(MM/64, (TT*BB)/64), 256>>>(p_Hb, Wo,           bo,      out, TT*BB, MM, DD, 0, BB, TT);
    sgemm<<<dim3(MM/64, (TT*BB)/64), 256>>>(p_Cb, Wo + DD*MM,   nullptr, out, TT*BB, MM, EE, 2, BB, TT);
    k_stop<<<(TT*BB)/8, 256>>>(Ws, bs, out);
}

// round 7
// speedup vs baseline: 1.1802x; 1.1802x over previous
#include <cuda_runtime.h>
#include <cuda_bf16.h>
#include <cuda_fp16.h>

#define BB 64
#define SS 512
#define EE 512
#define AA 256
#define HP 256
#define PP 128
#define DD 1024
#define MM 128
#define TT 800
#define G3 3072
#define NB 128
#define TPB 512
#define KT2 2688          /* PP+EE + 2*DD (parity-double h section) */
#define NKT 104
#define NCH 26

// ---------------- static scratch ----------------
__device__ __align__(128) __half g_epH[BB*SS*AA];            // 16.8MB fp16 enc_proj
__device__ __align__(128) __half g_encH[BB*SS*EE];           // 33.5MB fp16 encoder copy
__device__ __align__(128) float g_prev[TT*BB*MM];
__device__ __align__(128) float g_ph  [TT*BB*HP];
__device__ __align__(128) float g_pre [TT*BB*PP];
__device__ __align__(128) float g_h   [BB*DD];
__device__ __align__(128) float g_sc  [BB*SS];
__device__ __align__(128) float g_dpp [BB*NB*AA];            // [b][kpart][a]
__device__ __align__(128) __nv_bfloat16 g_Ah[BB*KT2];
__device__ __align__(128) __nv_bfloat16 g_Al[BB*KT2];
__device__ __align__(128) uint2 g_Wf[(size_t)NB*NKT*3*2*32];
__device__ __align__(128) float g_Hb  [(size_t)TT*BB*DD];
__device__ __align__(128) float g_Cb  [(size_t)TT*BB*EE];
__device__ __align__(128) volatile unsigned g_flags[NB*32];  // padded arrival flags
__device__ __align__(128) volatile unsigned g_pairf[NB*32];  // padded pair flags
__device__ volatile unsigned g_rel;

__device__ __forceinline__ float fsig(float x){
    float e = __expf(-x);
    return __fdividef(1.f, 1.f + e);
}
__device__ __forceinline__ float ftanh(float x){
    x = fminf(fmaxf(x, -15.f), 15.f);
    float e = __expf(2.f*x);
    return __fdividef(e - 1.f, e + 1.f);
}
__device__ __forceinline__ float tanh_mufu(float x){
    float y; asm("tanh.approx.f32 %0, %1;" : "=f"(y) : "f"(x)); return y;
}

// full grid barrier: parallel flag arrivals, single release word
__device__ __forceinline__ void gsync(unsigned &gen){
    gen++;
    __syncthreads();
    const int tid = threadIdx.x;
    if (blockIdx.x == 0){
        if (tid > 0 && tid < NB){
            while (g_flags[tid*32] < gen) {}
        }
        __syncthreads();
        if (tid == 0){ __threadfence(); g_rel = gen; }
    } else {
        if (tid == 0){
            __threadfence();
            g_flags[blockIdx.x*32] = gen;
            while (g_rel < gen) {}
            __threadfence();
        }
    }
    __syncthreads();
}

// pairwise barrier between blocks 2b and 2b+1
__device__ __forceinline__ void psync(unsigned &gen){
    gen++;
    __syncthreads();
    if (threadIdx.x == 0){
        __threadfence();
        g_pairf[blockIdx.x*32] = gen;
        while (g_pairf[(blockIdx.x^1)*32] < gen) {}
        __threadfence();
    }
    __syncthreads();
}

#define MMA(D0,D1,D2,D3,A0,A1,A2,A3,B0,B1) \
    asm volatile("mma.sync.aligned.m16n8k16.row.col.f32.bf16.bf16.f32 " \
        "{%0,%1,%2,%3},{%4,%5,%6,%7},{%8,%9},{%0,%1,%2,%3};" \
        : "+f"(D0),"+f"(D1),"+f"(D2),"+f"(D3) \
        : "r"(A0),"r"(A1),"r"(A2),"r"(A3),"r"(B0),"r"(B1))

// ---------------- generic tiled SGEMM (pre/epilogue only) ----------------
#define BKK 16
__global__ void sgemm(const float* __restrict__ A, const float* __restrict__ B,
                      const float* __restrict__ bias, float* __restrict__ C,
                      int M, int N, int K, int flags, int Bdim, int Tdim)
{
    __shared__ float As[BKK][64];
    __shared__ float Bs[BKK][64];
    const int n0 = blockIdx.x * 64;
    const int m0 = blockIdx.y * 64;
    const int tid = threadIdx.x;
    const int tx = tid & 15;
    const int ty = tid >> 4;
    float acc[4][4] = {};
    const int arow  = tid >> 2;
    const int acol4 = (tid & 3) * 4;
    const int brow  = tid >> 4;
    const int bcol4 = (tid & 15) * 4;

    for (int k = 0; k < K; k += BKK) {
        float4 av = *(const float4*)(A + (size_t)(m0 + arow) * K + k + acol4);
        As[acol4+0][arow] = av.x;
        As[acol4+1][arow] = av.y;
        As[acol4+2][arow] = av.z;
        As[acol4+3][arow] = av.w;
        float4 bvv = *(const float4*)(B + (size_t)(k + brow) * N + n0 + bcol4);
        *(float4*)(&Bs[brow][bcol4]) = bvv;
        __syncthreads();
        #pragma unroll
        for (int kk = 0; kk < BKK; kk++) {
            float4 a4 = *(const float4*)(&As[kk][ty*4]);
            float4 b4 = *(const float4*)(&Bs[kk][tx*4]);
            acc[0][0] += a4.x*b4.x; acc[0][1] += a4.x*b4.y; acc[0][2] += a4.x*b4.z; acc[0][3] += a4.x*b4.w;
            acc[1][0] += a4.y*b4.x; acc[1][1] += a4.y*b4.y; acc[1][2] += a4.y*b4.z; acc[1][3] += a4.y*b4.w;
            acc[2][0] += a4.z*b4.x; acc[2][1] += a4.z*b4.y; acc[2][2] += a4.z*b4.z; acc[2][3] += a4.z*b4.w;
            acc[3][0] += a4.w*b4.x; acc[3][1] += a4.w*b4.y; acc[3][2] += a4.w*b4.z; acc[3][3] += a4.w*b4.w;
        }
        __syncthreads();
    }
    #pragma unroll
    for (int i = 0; i < 4; i++) {
        const int m = m0 + ty*4 + i;
        #pragma unroll
        for (int j = 0; j < 4; j++) {
            const int n = n0 + tx*4 + j;
            float val = acc[i][j];
            if (bias) val += bias[n];
            if (flags & 1) val = fmaxf(val, 0.f);
            size_t idx;
            if (Bdim > 0) {
                const int bq = m % Bdim, tq = m / Bdim;
                idx = ((size_t)bq * Tdim + tq) * N + n;
            } else {
                idx = (size_t)m * N + n;
            }
            if (flags & 4)      ((__half*)C)[idx] = __float2half_rn(val);
            else if (flags & 2) C[idx] += val;
            else                C[idx] = val;
        }
    }
}

__global__ void k_init(){
    int i = blockIdx.x*256 + threadIdx.x;
    if (i < BB*NB*AA) g_dpp[i] = 0.f;
    if (i < BB*KT2){ g_Ah[i] = __float2bfloat16(0.f); g_Al[i] = __float2bfloat16(0.f); }
    if (i < BB*DD) g_h[i] = 0.f;
}

__global__ void k_prev(const float* __restrict__ tm){
    int i = blockIdx.x*256 + threadIdx.x;
    if (i >= TT*BB*MM) return;
    int m  = i & (MM-1);
    int tb = i >> 7;
    int b  = tb & (BB-1);
    int t  = tb >> 6;
    g_prev[i] = (t == 0) ? 0.f : tm[((size_t)b*TT + (t-1))*MM + m];
}

__global__ void k_convE(const float* __restrict__ enc){
    int i = blockIdx.x*256 + threadIdx.x;
    if (i < BB*SS*EE) g_encH[i] = __float2half_rn(enc[i]);
}

// pack [Wih; Whh] (K=1664 x N=3072) into mma B-fragment layout, bf16 hi/lo
__global__ void k_pack(const float* __restrict__ Wih, const float* __restrict__ Whh){
    int id = blockIdx.x*256 + threadIdx.x;
    const int TOTW = NB*NKT*3*32;
    if (id >= TOTW) return;
    int lane = id & 31; int r = id >> 5;
    int nt = r % 3; r /= 3;
    int kt = r % NKT; int blk = r / NKT;
    int g = lane >> 2, tig = lane & 3;
    int n = nt*DD + blk*8 + g;
    int k0 = kt*16;
    int kk[4] = {k0+2*tig, k0+2*tig+1, k0+8+2*tig, k0+9+2*tig};
    unsigned hh[4], ll[4];
    #pragma unroll
    for (int i=0;i<4;i++){
        int k = kk[i];
        float w = (k < PP+EE) ? Wih[(size_t)k*G3 + n] : Whh[(size_t)(k-(PP+EE))*G3 + n];
        __nv_bfloat16 hb = __float2bfloat16(w);
        __nv_bfloat16 lb = __float2bfloat16(w - __bfloat162float(hb));
        hh[i] = *(unsigned short*)&hb;
        ll[i] = *(unsigned short*)&lb;
    }
    size_t base = ((((size_t)blk*NKT + kt)*3 + nt)*2)*32 + lane;
    g_Wf[base]      = make_uint2((hh[1]<<16)|hh[0], (hh[3]<<16)|hh[2]);
    g_Wf[base + 32] = make_uint2((ll[1]<<16)|ll[0], (ll[3]<<16)|ll[2]);
}

__global__ void k_stop(const float* __restrict__ Ws, const float* __restrict__ bs,
                       float* __restrict__ dout){
    const int w = (blockIdx.x*blockDim.x + threadIdx.x) >> 5;
    const int lane = threadIdx.x & 31;
    if (w >= TT*BB) return;
    const float* hrow = g_Hb + (size_t)w*DD;
    const float* crow = g_Cb + (size_t)w*EE;
    float acc = 0.f;
    for (int k = lane; k < DD; k += 32) acc += hrow[k]*Ws[k];
    for (int k = lane; k < EE; k += 32) acc += crow[k]*Ws[DD+k];
    #pragma unroll
    for (int o = 16; o > 0; o >>= 1) acc += __shfl_down_sync(0xffffffffu, acc, o);
    if (lane == 0){
        const int tq = w / BB, bq = w % BB;
        dout[(size_t)BB*TT*MM + (size_t)bq*TT + tq] = acc + bs[0];
    }
}

// one phase-C chunk iteration: MMAs on current buffers, prefetch next into other buffers
#define CITER(c, BHc, BLc, BHn, BLn) { \
    const int cn = (c) + 1; \
    uint4 nvh, nvl; \
    if (cn < NCH){ \
        const int idx4 = (cn < 10) ? cn*8 : 80 + (cn-10)*8 + par*128; \
        nvh = ((const uint4*)g_Ah)[srow*336 + idx4 + sc4]; \
        nvl = ((const uint4*)g_Al)[srow*336 + idx4 + sc4]; \
        if (w < 12){ \
            size_t wb = ((((size_t)blk*NKT + cn*4)*3 + nt)*2)*32 + lane; \
            _Pragma("unroll") \
            for (int kl=0; kl<4; kl++){ \
                BHn[kl] = g_Wf[wb + (size_t)kl*192]; \
                BLn[kl] = g_Wf[wb + (size_t)kl*192 + 32]; \
            } \
        } \
    } \
    if (w < 12){ \
        const unsigned* Ah32 = smu + ((c)&1)*4608; \
        const unsigned* Al32 = Ah32 + 2304; \
        const bool useH = (nt == 2) && ((c) >= 10); \
        _Pragma("unroll") \
        for (int kl=0; kl<4; kl++){ \
            int r0 = (m0+g)*36 + kl*8 + tig; \
            unsigned a0 = Ah32[r0],   a1 = Ah32[r0+288]; \
            unsigned a2 = Ah32[r0+4], a3 = Ah32[r0+292]; \
            unsigned l0 = Al32[r0],   l1 = Al32[r0+288]; \
            unsigned l2 = Al32[r0+4], l3 = Al32[r0+292]; \
            if (useH){ \
                MMA(aH0,aH1,aH2,aH3, a0,a1,a2,a3, BHc[kl].x, BHc[kl].y); \
                MMA(aH0,aH1,aH2,aH3, a0,a1,a2,a3, BLc[kl].x, BLc[kl].y); \
                MMA(aH0,aH1,aH2,aH3, l0,l1,l2,l3, BHc[kl].x, BHc[kl].y); \
            } else { \
                MMA(aX0,aX1,aX2,aX3, a0,a1,a2,a3, BHc[kl].x, BHc[kl].y); \
                MMA(aX0,aX1,aX2,aX3, a0,a1,a2,a3, BLc[kl].x, BLc[kl].y); \
                MMA(aX0,aX1,aX2,aX3, l0,l1,l2,l3, BHc[kl].x, BHc[kl].y); \
            } \
        } \
    } \
    if (cn < NCH){ \
        unsigned boff = (cn&1)*4608; \
        ((uint4*)(smu + boff))[srow*9 + sc4] = nvh; \
        ((uint4*)(smu + boff + 2304))[srow*9 + sc4] = nvl; \
    } \
    __syncthreads(); \
}

// ================= persistent decode kernel =================
__global__ void __launch_bounds__(TPB)
decode(const float* __restrict__ Wd,  const float* __restrict__ bd,
       const float* __restrict__ v,   const float* __restrict__ bv,
       const float* __restrict__ bih, const float* __restrict__ bhh,
       float* __restrict__ out)
{
    __shared__ float sm[9216];
    const int blk = blockIdx.x, tid = threadIdx.x;
    const int lane = tid & 31, wq = tid >> 5;
    unsigned gen = g_rel;

    for (int t = 0; t < TT; t++){
        const int par = t & 1;
        // ---------- A: dp partial-sum + attention scores ----------
        {
            const int b = blk >> 1, sh = blk & 1;
            float* dps = sm; float* vs = sm + 256; float* part = sm + 512;
            {
                const int a = tid & 255, jh = tid >> 8;
                const float* pp = g_dpp + ((size_t)b*NB + jh*64)*AA + a;
                float s = 0.f;
                #pragma unroll 16
                for (int j = 0; j < 64; j++) s += pp[(size_t)j*AA];
                part[tid] = s;
            }
            if (sh == 0 && tid >= 384){
                int m = tid - 384;
                float pv = g_pre[((size_t)t*BB + b)*PP + m];
                __nv_bfloat16 hb = __float2bfloat16(pv);
                g_Ah[b*KT2 + m] = hb;
                g_Al[b*KT2 + m] = __float2bfloat16(pv - __bfloat162float(hb));
            }
            __syncthreads();
            if (tid < 256){ dps[tid] = part[tid] + part[256+tid] + bd[tid]; vs[tid] = v[tid]; }
            __syncthreads();
            const int sl = tid >> 1, ah = tid & 1;
            const int s = sh*256 + sl;
            const uint4* ep4 = (const uint4*)(g_epH + ((size_t)(b*SS + s))*AA + ah*128);
            const float* dp2 = dps + ah*128;
            const float* v2  = vs  + ah*128;
            float acc = 0.f;
            #pragma unroll 4
            for (int q = 0; q < 16; q++){
                uint4 u = ep4[q];
                float2 f0 = __half22float2(*(__half2*)&u.x);
                float2 f1 = __half22float2(*(__half2*)&u.y);
                float2 f2 = __half22float2(*(__half2*)&u.z);
                float2 f3 = __half22float2(*(__half2*)&u.w);
                const int i0 = q*8;
                acc += v2[i0+0]*tanh_mufu(f0.x + dp2[i0+0]);
                acc += v2[i0+1]*tanh_mufu(f0.y + dp2[i0+1]);
                acc += v2[i0+2]*tanh_mufu(f1.x + dp2[i0+2]);
                acc += v2[i0+3]*tanh_mufu(f1.y + dp2[i0+3]);
                acc += v2[i0+4]*tanh_mufu(f2.x + dp2[i0+4]);
                acc += v2[i0+5]*tanh_mufu(f2.y + dp2[i0+5]);
                acc += v2[i0+6]*tanh_mufu(f3.x + dp2[i0+6]);
                acc += v2[i0+7]*tanh_mufu(f3.y + dp2[i0+7]);
            }
            acc += __shfl_xor_sync(0xffffffffu, acc, 1);
            if (ah == 0) g_sc[b*SS + s] = acc + bv[0];
            __syncthreads();
        }
        psync(gen);
        // ---------- B: softmax + context ----------
        {
            const int b = blk >> 1, eh = blk & 1;
            float* aw = sm; float* sm2 = sm + 512; float* red = sm + 1536;
            float sc = g_sc[b*SS + tid];
            float mx = sc;
            #pragma unroll
            for (int o = 16; o; o >>= 1) mx = fmaxf(mx, __shfl_xor_sync(0xffffffffu, mx, o));
            if (lane == 0) red[wq] = mx;
            __syncthreads();
            if (tid < 32){
                float mm = (tid < 16) ? red[tid] : -1e30f;
                #pragma unroll
                for (int o = 8; o; o >>= 1) mm = fmaxf(mm, __shfl_xor_sync(0xffffffffu, mm, o));
                if (tid == 0) red[16] = mm;
            }
            __syncthreads();
            mx = red[16];
            float ev = __expf(sc - mx);
            float ss = ev;
            #pragma unroll
            for (int o = 16; o; o >>= 1) ss += __shfl_xor_sync(0xffffffffu, ss, o);
            if (lane == 0) red[wq] = ss;
            __syncthreads();
            if (tid < 32){
                float s2 = (tid < 16) ? red[tid] : 0.f;
                #pragma unroll
                for (int o = 8; o; o >>= 1) s2 += __shfl_xor_sync(0xffffffffu, s2, o);
                if (tid == 0) red[17] = s2;
            }
            __syncthreads();
            const float inv = __fdividef(1.f, red[17]);
            float a = ev * inv;
            aw[tid] = a;
            if (eh == 0)
                out[(size_t)BB*TT*MM + (size_t)BB*TT + ((size_t)b*TT + t)*SS + tid] = a;
            __syncthreads();
            const int el = tid & 127, shalf = tid >> 7;
            const __half2* eb = (const __half2*)(g_encH + ((size_t)(b*SS + shalf*128))*EE + eh*256 + el*2);
            const float* awq = aw + shalf*128;
            float c0 = 0.f, c1 = 0.f;
            #pragma unroll 8
            for (int s2 = 0; s2 < 128; s2++){
                float2 e = __half22float2(eb[(size_t)s2*(EE/2)]);
                float a2 = awq[s2];
                c0 += a2*e.x; c1 += a2*e.y;
            }
            sm2[shalf*256 + el*2]     = c0;
            sm2[shalf*256 + el*2 + 1] = c1;
            __syncthreads();
            if (tid < 256){
                float cc = sm2[tid] + sm2[256+tid] + sm2[512+tid] + sm2[768+tid];
                const int e2 = eh*256 + tid;
                g_Cb[((size_t)t*BB + b)*EE + e2] = cc;
                __nv_bfloat16 hb = __float2bfloat16(cc);
                g_Ah[b*KT2 + PP + e2] = hb;
                g_Al[b*KT2 + PP + e2] = __float2bfloat16(cc - __bfloat162float(hb));
            }
            __syncthreads();
        }
        gsync(gen);
        // ---------- C: gates mma GEMM + GRU + dp partials ----------
        {
            const int w = wq;
            const int g = lane >> 2, tig = lane & 3;
            const int nt = w >> 2;
            const int m0 = (w & 3) * 16;
            float aX0=0,aX1=0,aX2=0,aX3=0, aH0=0,aH1=0,aH2=0,aH3=0;
            uint2 bh0[4], bl0[4], bh1[4], bl1[4];
            const int srow = tid >> 3, sc4 = tid & 7;
            unsigned* smu = (unsigned*)sm;
            {
                uint4 vh = ((const uint4*)g_Ah)[srow*336 + sc4];
                uint4 vl = ((const uint4*)g_Al)[srow*336 + sc4];
                ((uint4*)smu)[srow*9 + sc4] = vh;
                ((uint4*)(smu + 2304))[srow*9 + sc4] = vl;
                if (w < 12){
                    size_t wb = (((size_t)blk*NKT*3 + nt)*2)*32 + lane;
                    #pragma unroll
                    for (int kl=0; kl<4; kl++){
                        bh0[kl] = g_Wf[wb + (size_t)kl*192];
                        bl0[kl] = g_Wf[wb + (size_t)kl*192 + 32];
                    }
                }
            }
            __syncthreads();
            for (int c2 = 0; c2 < NCH; c2 += 2){
                CITER(c2,   bh0, bl0, bh1, bl1)
                CITER(c2+1, bh1, bl1, bh0, bl0)
            }
            // gate frags -> smem planes [4][64][8]
            float* sg = sm;
            if (w < 12){
                float* pl = sg + nt*512;
                int rr = (m0+g)*8 + 2*tig;
                pl[rr]=aX0; pl[rr+1]=aX1; pl[rr+64]=aX2; pl[rr+65]=aX3;
                if (nt == 2){
                    float* p3 = sg + 3*512;
                    p3[rr]=aH0; p3[rr+1]=aH1; p3[rr+64]=aH2; p3[rr+65]=aH3;
                }
            }
            float* Wds = sm + 2048; float* hs = sm + 4096;
            {
                const int row = tid >> 6, c4 = (tid & 63)*4;
                *(float4*)(Wds + row*256 + c4) = *(const float4*)(Wd + (size_t)(blk*8+row)*AA + c4);
            }
            __syncthreads();
            // GRU pointwise
            {
                const int b = tid >> 3, dl = tid & 7, d = blk*8 + dl;
                float gr  = sg[b*8+dl]        + bih[d] + bhh[d];
                float gz  = sg[512 + b*8+dl]  + bih[DD+d] + bhh[DD+d];
                float gin = sg[1024 + b*8+dl] + bih[2*DD+d];
                float ghn = sg[1536 + b*8+dl] + bhh[2*DD+d];
                float r = fsig(gr), z = fsig(gz);
                float n = ftanh(gin + r*ghn);
                float h = g_h[b*DD + d];
                float hn = (1.f - z)*n + z*h;
                g_h[b*DD + d] = hn;
                g_Hb[((size_t)t*BB + b)*DD + d] = hn;
                __nv_bfloat16 hb = __float2bfloat16(hn);
                const int hoff = PP+EE + ((t+1)&1)*DD + d;
                g_Ah[b*KT2 + hoff] = hb;
                g_Al[b*KT2 + hoff] = __float2bfloat16(hn - __bfloat162float(hb));
                hs[b*8 + dl] = hn;
            }
            __syncthreads();
            // dp k-partials for next step (this block's 8 d's), [b][blk][a] layout
            {
                const int bg = tid >> 5, ag = tid & 31;
                const int b4 = bg*4, a8 = ag*8;
                float acc[4][8] = {};
                #pragma unroll
                for (int kk = 0; kk < 8; kk++){
                    const float4 w0 = *(const float4*)(Wds + kk*256 + a8);
                    const float4 w1 = *(const float4*)(Wds + kk*256 + a8 + 4);
                    #pragma unroll
                    for (int i = 0; i < 4; i++){
                        const float h = hs[(b4+i)*8 + kk];
                        acc[i][0]+=h*w0.x; acc[i][1]+=h*w0.y; acc[i][2]+=h*w0.z; acc[i][3]+=h*w0.w;
                        acc[i][4]+=h*w1.x; acc[i][5]+=h*w1.y; acc[i][6]+=h*w1.z; acc[i][7]+=h*w1.w;
                    }
                }
                #pragma unroll
                for (int i = 0; i < 4; i++){
                    float* o = g_dpp + ((size_t)(b4+i)*NB + blk)*AA + a8;
                    *(float4*)(o)   = make_float4(acc[i][0],acc[i][1],acc[i][2],acc[i][3]);
                    *(float4*)(o+4) = make_float4(acc[i][4],acc[i][5],acc[i][6],acc[i][7]);
                }
            }
        }
        gsync(gen);
    }
}

// ---------------- host ----------------
extern "C" void kernel_launch(void* const* d_in, const int* in_sizes, int n_in,
                              void* d_out, int out_size){
    const float* enc = (const float*)d_in[0];
    const float* tm  = (const float*)d_in[1];
    const float* We  = (const float*)d_in[2];
    const float* be  = (const float*)d_in[3];
    const float* Wd  = (const float*)d_in[4];
    const float* bd  = (const float*)d_in[5];
    const float* v   = (const float*)d_in[6];
    const float* bv  = (const float*)d_in[7];
    const float* W1  = (const float*)d_in[8];
    const float* b1  = (const float*)d_in[9];
    const float* W2  = (const float*)d_in[10];
    const float* b2  = (const float*)d_in[11];
    const float* Wih = (const float*)d_in[12];
    const float* bih = (const float*)d_in[13];
    const float* Whh = (const float*)d_in[14];
    const float* bhh = (const float*)d_in[15];
    const float* Wo  = (const float*)d_in[16];
    const float* bo  = (const float*)d_in[17];
    const float* Ws  = (const float*)d_in[18];
    const float* bs  = (const float*)d_in[19];
    float* out = (float*)d_out;

    float *p_prev, *p_ph, *p_pre, *p_Hb, *p_Cb; __half *p_epH;
    cudaGetSymbolAddress((void**)&p_epH,  g_epH);
    cudaGetSymbolAddress((void**)&p_prev, g_prev);
    cudaGetSymbolAddress((void**)&p_ph,   g_ph);
    cudaGetSymbolAddress((void**)&p_pre,  g_pre);
    cudaGetSymbolAddress((void**)&p_Hb,   g_Hb);
    cudaGetSymbolAddress((void**)&p_Cb,   g_Cb);

    // precompute
    k_init<<<(BB*NB*AA + 255)/256, 256>>>();
    k_prev<<<(TT*BB*MM + 255)/256, 256>>>(tm);
    k_convE<<<(BB*SS*EE + 255)/256, 256>>>(enc);
    k_pack<<<(NB*NKT*3*32 + 255)/256, 256>>>(Wih, Whh);
    sgemm<<<dim3(HP/64, (TT*BB)/64), 256>>>(p_prev, W1, b1, p_ph,  TT*BB, HP, MM, 1, 0, 0);
    sgemm<<<dim3(PP/64, (TT*BB)/64), 256>>>(p_ph,   W2, b2, p_pre, TT*BB, PP, HP, 1, 0, 0);
    sgemm<<<dim3(AA/64, (BB*SS)/64), 256>>>(enc,    We, be, (float*)p_epH, BB*SS, AA, EE, 4, 0, 0);

    // sequential decode: one persistent kernel
    decode<<<NB, TPB>>>(Wd, bd, v, bv, bih, bhh, out);

    // output heads
    sgemm<<<dim3(MM/64, (TT*BB)/64), 256>>>(p_Hb, Wo,           bo,      out, TT*BB, MM, DD, 0, BB, TT);
    sgemm<<<dim3(MM/64, (TT*BB)/64), 256>>>(p_Cb, Wo + DD*MM,   nullptr, out, TT*BB, MM, EE, 2, BB, TT);
    k_stop<<<(TT*BB)/8, 256>>>(Ws, bs, out);
}

// round 8
// speedup vs baseline: 1.3133x; 1.1127x over previous
#include <cuda_runtime.h>
#include <cuda_bf16.h>
#include <cuda_fp16.h>

#define BB 64
#define SS 512
#define EE 512
#define AA 256
#define HP 256
#define PP 128
#define DD 1024
#define MM 128
#define TT 800
#define G3 3072
#define NB 128
#define TPB 512
#define KT2 2688          /* PP+EE + 2*DD (parity-double h section) */
#define NCHT 26           /* total 64-k chunks */
#define NCHH 13           /* chunks per block (k-split pair) */
#define WBLOB 1536        /* uint2 per W chunk blob */

// ---------------- static scratch ----------------
__device__ __align__(128) __half g_epH[BB*SS*AA];
__device__ __align__(128) __half g_encH[BB*SS*EE];
__device__ __align__(128) float g_prev[TT*BB*MM];
__device__ __align__(128) float g_ph  [TT*BB*HP];
__device__ __align__(128) float g_pre [TT*BB*PP];
__device__ __align__(128) float g_h   [BB*DD];
__device__ __align__(128) float g_sc  [BB*SS];
__device__ __align__(128) float g_dpp [BB*NB*AA];
__device__ __align__(128) __nv_bfloat16 g_Ah[BB*KT2];
__device__ __align__(128) __nv_bfloat16 g_Al[BB*KT2];
__device__ __align__(128) uint2 g_Wf2[(size_t)64*NCHT*WBLOB];   // 20.4MB chunk-blob weights
__device__ __align__(128) float g_gp  [NB*4*64*16];             // 2MB gate partials
__device__ __align__(128) float g_Hb  [(size_t)TT*BB*DD];
__device__ __align__(128) float g_Cb  [(size_t)TT*BB*EE];
__device__ __align__(128) volatile unsigned g_flags[NB*32];
__device__ __align__(128) volatile unsigned g_pairf[NB*32];
__device__ volatile unsigned g_rel;

__device__ __forceinline__ float fsig(float x){
    float e = __expf(-x);
    return __fdividef(1.f, 1.f + e);
}
__device__ __forceinline__ float ftanh(float x){
    x = fminf(fmaxf(x, -15.f), 15.f);
    float e = __expf(2.f*x);
    return __fdividef(e - 1.f, e + 1.f);
}
__device__ __forceinline__ float tanh_mufu(float x){
    float y; asm("tanh.approx.f32 %0, %1;" : "=f"(y) : "f"(x)); return y;
}

// full grid barrier
__device__ __forceinline__ void gsync(unsigned &gen){
    gen++;
    __syncthreads();
    const int tid = threadIdx.x;
    if (blockIdx.x == 0){
        if (tid > 0 && tid < NB){
            while (g_flags[tid*32] < gen) {}
        }
        __syncthreads();
        if (tid == 0){ __threadfence(); g_rel = gen; }
    } else {
        if (tid == 0){
            __threadfence();
            g_flags[blockIdx.x*32] = gen;
            while (g_rel < gen) {}
            __threadfence();
        }
    }
    __syncthreads();
}

// pairwise barrier between blocks 2p and 2p+1
__device__ __forceinline__ void psync(unsigned &gen){
    gen++;
    __syncthreads();
    if (threadIdx.x == 0){
        __threadfence();
        g_pairf[blockIdx.x*32] = gen;
        while (g_pairf[(blockIdx.x^1)*32] < gen) {}
        __threadfence();
    }
    __syncthreads();
}

#define MMA(D0,D1,D2,D3,A0,A1,A2,A3,B0,B1) \
    asm volatile("mma.sync.aligned.m16n8k16.row.col.f32.bf16.bf16.f32 " \
        "{%0,%1,%2,%3},{%4,%5,%6,%7},{%8,%9},{%0,%1,%2,%3};" \
        : "+f"(D0),"+f"(D1),"+f"(D2),"+f"(D3) \
        : "r"(A0),"r"(A1),"r"(A2),"r"(A3),"r"(B0),"r"(B1))

// ---------------- generic tiled SGEMM (pre/epilogue only) ----------------
#define BKK 16
__global__ void sgemm(const float* __restrict__ A, const float* __restrict__ B,
                      const float* __restrict__ bias, float* __restrict__ C,
                      int M, int N, int K, int flags, int Bdim, int Tdim)
{
    __shared__ float As[BKK][64];
    __shared__ float Bs[BKK][64];
    const int n0 = blockIdx.x * 64;
    const int m0 = blockIdx.y * 64;
    const int tid = threadIdx.x;
    const int tx = tid & 15;
    const int ty = tid >> 4;
    float acc[4][4] = {};
    const int arow  = tid >> 2;
    const int acol4 = (tid & 3) * 4;
    const int brow  = tid >> 4;
    const int bcol4 = (tid & 15) * 4;

    for (int k = 0; k < K; k += BKK) {
        float4 av = *(const float4*)(A + (size_t)(m0 + arow) * K + k + acol4);
        As[acol4+0][arow] = av.x;
        As[acol4+1][arow] = av.y;
        As[acol4+2][arow] = av.z;
        As[acol4+3][arow] = av.w;
        float4 bvv = *(const float4*)(B + (size_t)(k + brow) * N + n0 + bcol4);
        *(float4*)(&Bs[brow][bcol4]) = bvv;
        __syncthreads();
        #pragma unroll
        for (int kk = 0; kk < BKK; kk++) {
            float4 a4 = *(const float4*)(&As[kk][ty*4]);
            float4 b4 = *(const float4*)(&Bs[kk][tx*4]);
            acc[0][0] += a4.x*b4.x; acc[0][1] += a4.x*b4.y; acc[0][2] += a4.x*b4.z; acc[0][3] += a4.x*b4.w;
            acc[1][0] += a4.y*b4.x; acc[1][1] += a4.y*b4.y; acc[1][2] += a4.y*b4.z; acc[1][3] += a4.y*b4.w;
            acc[2][0] += a4.z*b4.x; acc[2][1] += a4.z*b4.y; acc[2][2] += a4.z*b4.z; acc[2][3] += a4.z*b4.w;
            acc[3][0] += a4.w*b4.x; acc[3][1] += a4.w*b4.y; acc[3][2] += a4.w*b4.z; acc[3][3] += a4.w*b4.w;
        }
        __syncthreads();
    }
    #pragma unroll
    for (int i = 0; i < 4; i++) {
        const int m = m0 + ty*4 + i;
        #pragma unroll
        for (int j = 0; j < 4; j++) {
            const int n = n0 + tx*4 + j;
            float val = acc[i][j];
            if (bias) val += bias[n];
            if (flags & 1) val = fmaxf(val, 0.f);
            size_t idx;
            if (Bdim > 0) {
                const int bq = m % Bdim, tq = m / Bdim;
                idx = ((size_t)bq * Tdim + tq) * N + n;
            } else {
                idx = (size_t)m * N + n;
            }
            if (flags & 4)      ((__half*)C)[idx] = __float2half_rn(val);
            else if (flags & 2) C[idx] += val;
            else                C[idx] = val;
        }
    }
}

__global__ void k_init(){
    int i = blockIdx.x*256 + threadIdx.x;
    if (i < BB*NB*AA) g_dpp[i] = 0.f;
    if (i < BB*KT2){ g_Ah[i] = __float2bfloat16(0.f); g_Al[i] = __float2bfloat16(0.f); }
    if (i < BB*DD) g_h[i] = 0.f;
}

__global__ void k_prev(const float* __restrict__ tm){
    int i = blockIdx.x*256 + threadIdx.x;
    if (i >= TT*BB*MM) return;
    int m  = i & (MM-1);
    int tb = i >> 7;
    int b  = tb & (BB-1);
    int t  = tb >> 6;
    g_prev[i] = (t == 0) ? 0.f : tm[((size_t)b*TT + (t-1))*MM + m];
}

__global__ void k_convE(const float* __restrict__ enc){
    int i = blockIdx.x*256 + threadIdx.x;
    if (i < BB*SS*EE) g_encH[i] = __float2half_rn(enc[i]);
}

// pack [Wih; Whh] into per-(pair,chunk) contiguous blobs of mma B-fragments (bf16 hi/lo)
__global__ void k_pack(const float* __restrict__ Wih, const float* __restrict__ Whh){
    int id = blockIdx.x*256 + threadIdx.x;
    const int TOTW = 64*NCHT*WBLOB;
    if (id >= TOTW) return;
    const int lane = id & 31;
    const int hl   = (id >> 5) & 1;
    const int kl   = (id >> 6) & 3;
    const int j    = (id >> 8) & 1;
    const int idx2 = id % WBLOB;
    const int nt   = idx2 >> 9;             // 0..2
    const int c    = (id / WBLOB) % NCHT;
    const int pair = id / (WBLOB*NCHT);
    const int tig = lane & 3;
    const int n = nt*DD + pair*16 + j*8 + (lane >> 2);
    const int k0 = c*64 + kl*16;
    int kk[4] = {k0+2*tig, k0+2*tig+1, k0+8+2*tig, k0+9+2*tig};
    unsigned q[4];
    #pragma unroll
    for (int i2=0;i2<4;i2++){
        int k = kk[i2];
        float w = (k < PP+EE) ? Wih[(size_t)k*G3 + n] : Whh[(size_t)(k-(PP+EE))*G3 + n];
        __nv_bfloat16 hb = __float2bfloat16(w);
        if (hl){
            __nv_bfloat16 lb = __float2bfloat16(w - __bfloat162float(hb));
            q[i2] = *(unsigned short*)&lb;
        } else {
            q[i2] = *(unsigned short*)&hb;
        }
    }
    g_Wf2[id] = make_uint2((q[1]<<16)|q[0], (q[3]<<16)|q[2]);
}

__global__ void k_stop(const float* __restrict__ Ws, const float* __restrict__ bs,
                       float* __restrict__ dout){
    const int w = (blockIdx.x*blockDim.x + threadIdx.x) >> 5;
    const int lane = threadIdx.x & 31;
    if (w >= TT*BB) return;
    const float* hrow = g_Hb + (size_t)w*DD;
    const float* crow = g_Cb + (size_t)w*EE;
    float acc = 0.f;
    for (int k = lane; k < DD; k += 32) acc += hrow[k]*Ws[k];
    for (int k = lane; k < EE; k += 32) acc += crow[k]*Ws[DD+k];
    #pragma unroll
    for (int o = 16; o > 0; o >>= 1) acc += __shfl_down_sync(0xffffffffu, acc, o);
    if (lane == 0){
        const int tq = w / BB, bq = w % BB;
        dout[(size_t)BB*TT*MM + (size_t)bq*TT + tq] = acc + bs[0];
    }
}

// ================= persistent decode kernel =================
// dynamic smem layout (unsigned units):
//   A buf0 [0,4608)  A buf1 [4608,9216)   (each: 2304 hi + 2304 lo)
//   W buf0 [9216,12288)  W buf1 [12288,15360)
__global__ void __launch_bounds__(TPB)
decode(const float* __restrict__ Wd,  const float* __restrict__ bd,
       const float* __restrict__ v,   const float* __restrict__ bv,
       const float* __restrict__ bih, const float* __restrict__ bhh,
       float* __restrict__ out)
{
    extern __shared__ float smf[];
    unsigned* smu = (unsigned*)smf;
    const int blk = blockIdx.x, tid = threadIdx.x;
    const int lane = tid & 31, wq = tid >> 5;
    unsigned gen = g_rel;

    const int pair = blk >> 1, ks = blk & 1;
    const int cbeg = ks * NCHH;
    const uint2* Wsrc = g_Wf2 + (size_t)pair*NCHT*WBLOB;

    for (int t = 0; t < TT; t++){
        const int par = t & 1;
        // ---------- A: dp partial-sum + attention scores ----------
        {
            const int b = blk >> 1, sh = blk & 1;
            float* dps = smf; float* vs = smf + 256; float* part = smf + 512;
            {
                const int a = tid & 255, jh = tid >> 8;
                const float* pp = g_dpp + ((size_t)b*NB + jh*64)*AA + a;
                float s = 0.f;
                #pragma unroll 16
                for (int j = 0; j < 64; j++) s += pp[(size_t)j*AA];
                part[tid] = s;
            }
            if (sh == 0 && tid >= 384){
                int m = tid - 384;
                float pv = g_pre[((size_t)t*BB + b)*PP + m];
                __nv_bfloat16 hb = __float2bfloat16(pv);
                g_Ah[b*KT2 + m] = hb;
                g_Al[b*KT2 + m] = __float2bfloat16(pv - __bfloat162float(hb));
            }
            __syncthreads();
            if (tid < 256){ dps[tid] = part[tid] + part[256+tid] + bd[tid]; vs[tid] = v[tid]; }
            __syncthreads();
            const int sl = tid >> 1, ah = tid & 1;
            const int s = sh*256 + sl;
            const uint4* ep4 = (const uint4*)(g_epH + ((size_t)(b*SS + s))*AA + ah*128);
            const float* dp2 = dps + ah*128;
            const float* v2  = vs  + ah*128;
            float acc = 0.f;
            #pragma unroll 4
            for (int q = 0; q < 16; q++){
                uint4 u = ep4[q];
                float2 f0 = __half22float2(*(__half2*)&u.x);
                float2 f1 = __half22float2(*(__half2*)&u.y);
                float2 f2 = __half22float2(*(__half2*)&u.z);
                float2 f3 = __half22float2(*(__half2*)&u.w);
                const int i0 = q*8;
                acc += v2[i0+0]*tanh_mufu(f0.x + dp2[i0+0]);
                acc += v2[i0+1]*tanh_mufu(f0.y + dp2[i0+1]);
                acc += v2[i0+2]*tanh_mufu(f1.x + dp2[i0+2]);
                acc += v2[i0+3]*tanh_mufu(f1.y + dp2[i0+3]);
                acc += v2[i0+4]*tanh_mufu(f2.x + dp2[i0+4]);
                acc += v2[i0+5]*tanh_mufu(f2.y + dp2[i0+5]);
                acc += v2[i0+6]*tanh_mufu(f3.x + dp2[i0+6]);
                acc += v2[i0+7]*tanh_mufu(f3.y + dp2[i0+7]);
            }
            acc += __shfl_xor_sync(0xffffffffu, acc, 1);
            if (ah == 0) g_sc[b*SS + s] = acc + bv[0];
            __syncthreads();
        }
        psync(gen);
        // ---------- B: softmax + context ----------
        {
            const int b = blk >> 1, eh = blk & 1;
            float* aw = smf; float* sm2 = smf + 512; float* red = smf + 1536;
            float sc = g_sc[b*SS + tid];
            float mx = sc;
            #pragma unroll
            for (int o = 16; o; o >>= 1) mx = fmaxf(mx, __shfl_xor_sync(0xffffffffu, mx, o));
            if (lane == 0) red[wq] = mx;
            __syncthreads();
            if (tid < 32){
                float mm = (tid < 16) ? red[tid] : -1e30f;
                #pragma unroll
                for (int o = 8; o; o >>= 1) mm = fmaxf(mm, __shfl_xor_sync(0xffffffffu, mm, o));
                if (tid == 0) red[16] = mm;
            }
            __syncthreads();
            mx = red[16];
            float ev = __expf(sc - mx);
            float ss = ev;
            #pragma unroll
            for (int o = 16; o; o >>= 1) ss += __shfl_xor_sync(0xffffffffu, ss, o);
            if (lane == 0) red[wq] = ss;
            __syncthreads();
            if (tid < 32){
                float s2 = (tid < 16) ? red[tid] : 0.f;
                #pragma unroll
                for (int o = 8; o; o >>= 1) s2 += __shfl_xor_sync(0xffffffffu, s2, o);
                if (tid == 0) red[17] = s2;
            }
            __syncthreads();
            const float inv = __fdividef(1.f, red[17]);
            float a = ev * inv;
            aw[tid] = a;
            if (eh == 0)
                out[(size_t)BB*TT*MM + (size_t)BB*TT + ((size_t)b*TT + t)*SS + tid] = a;
            __syncthreads();
            const int el = tid & 127, shalf = tid >> 7;
            const __half2* eb = (const __half2*)(g_encH + ((size_t)(b*SS + shalf*128))*EE + eh*256 + el*2);
            const float* awq = aw + shalf*128;
            float c0 = 0.f, c1 = 0.f;
            #pragma unroll 8
            for (int s2 = 0; s2 < 128; s2++){
                float2 e = __half22float2(eb[(size_t)s2*(EE/2)]);
                float a2 = awq[s2];
                c0 += a2*e.x; c1 += a2*e.y;
            }
            sm2[shalf*256 + el*2]     = c0;
            sm2[shalf*256 + el*2 + 1] = c1;
            __syncthreads();
            if (tid < 256){
                float cc = sm2[tid] + sm2[256+tid] + sm2[512+tid] + sm2[768+tid];
                const int e2 = eh*256 + tid;
                g_Cb[((size_t)t*BB + b)*EE + e2] = cc;
                __nv_bfloat16 hb = __float2bfloat16(cc);
                g_Ah[b*KT2 + PP + e2] = hb;
                g_Al[b*KT2 + PP + e2] = __float2bfloat16(cc - __bfloat162float(hb));
            }
            __syncthreads();
        }
        gsync(gen);
        // ---------- C: gates mma GEMM (pairwise K-split, 48 n-cols/block) ----------
        {
            const int g = lane >> 2, tig = lane & 3;
            const int nt = wq >> 2;                 // gate (valid for wq<12)
            const int m0 = (wq & 3) * 16;
            const bool mma_on = (wq < 12);
            float aX[2][4] = {}, aH[2][4] = {};
            const int srow = tid >> 3, sc4 = tid & 7;

            // preload chunk cbeg into buf 0
            {
                const int c = cbeg;
                const int idx4 = (c < 10) ? c*8 : 80 + (c-10)*8 + par*128;
                uint4 vh = ((const uint4*)g_Ah)[srow*336 + idx4 + sc4];
                uint4 vl = ((const uint4*)g_Al)[srow*336 + idx4 + sc4];
                ((uint4*)smu)[srow*9 + sc4] = vh;
                ((uint4*)(smu + 2304))[srow*9 + sc4] = vl;
                uint2* wb = (uint2*)(smu + 9216);
                wb[tid]       = Wsrc[(size_t)c*WBLOB + tid];
                wb[tid + 512] = Wsrc[(size_t)c*WBLOB + tid + 512];
                wb[tid + 1024]= Wsrc[(size_t)c*WBLOB + tid + 1024];
            }
            __syncthreads();
            for (int i = 0; i < NCHH; i++){
                uint4 nvh, nvl; uint2 nw0, nw1, nw2;
                if (i + 1 < NCHH){
                    const int cn = cbeg + i + 1;
                    const int idx4 = (cn < 10) ? cn*8 : 80 + (cn-10)*8 + par*128;
                    nvh = ((const uint4*)g_Ah)[srow*336 + idx4 + sc4];
                    nvl = ((const uint4*)g_Al)[srow*336 + idx4 + sc4];
                    nw0 = Wsrc[(size_t)cn*WBLOB + tid];
                    nw1 = Wsrc[(size_t)cn*WBLOB + tid + 512];
                    nw2 = Wsrc[(size_t)cn*WBLOB + tid + 1024];
                }
                if (mma_on){
                    const unsigned* Ah32 = smu + (i&1)*4608;
                    const unsigned* Al32 = Ah32 + 2304;
                    const uint2* Wq = (const uint2*)(smu + 9216 + (i&1)*3072) + nt*512;
                    const bool useH = (nt == 2) && ((cbeg + i) >= 10);
                    #pragma unroll
                    for (int kl = 0; kl < 4; kl++){
                        const int r0 = (m0+g)*36 + kl*8 + tig;
                        unsigned a0 = Ah32[r0],   a1 = Ah32[r0+288];
                        unsigned a2 = Ah32[r0+4], a3 = Ah32[r0+292];
                        unsigned l0 = Al32[r0],   l1 = Al32[r0+288];
                        unsigned l2 = Al32[r0+4], l3 = Al32[r0+292];
                        #pragma unroll
                        for (int j = 0; j < 2; j++){
                            uint2 bh = Wq[j*256 + kl*64 + lane];
                            uint2 bl = Wq[j*256 + kl*64 + 32 + lane];
                            if (useH){
                                MMA(aH[j][0],aH[j][1],aH[j][2],aH[j][3], a0,a1,a2,a3, bh.x,bh.y);
                                MMA(aH[j][0],aH[j][1],aH[j][2],aH[j][3], a0,a1,a2,a3, bl.x,bl.y);
                                MMA(aH[j][0],aH[j][1],aH[j][2],aH[j][3], l0,l1,l2,l3, bh.x,bh.y);
                            } else {
                                MMA(aX[j][0],aX[j][1],aX[j][2],aX[j][3], a0,a1,a2,a3, bh.x,bh.y);
                                MMA(aX[j][0],aX[j][1],aX[j][2],aX[j][3], a0,a1,a2,a3, bl.x,bl.y);
                                MMA(aX[j][0],aX[j][1],aX[j][2],aX[j][3], l0,l1,l2,l3, bh.x,bh.y);
                            }
                        }
                    }
                }
                if (i + 1 < NCHH){
                    const unsigned boff = ((i+1)&1)*4608;
                    ((uint4*)(smu + boff))[srow*9 + sc4] = nvh;
                    ((uint4*)(smu + boff + 2304))[srow*9 + sc4] = nvl;
                    uint2* wb = (uint2*)(smu + 9216 + ((i+1)&1)*3072);
                    wb[tid] = nw0; wb[tid + 512] = nw1; wb[tid + 1024] = nw2;
                }
                __syncthreads();
            }
            // write gate partials to global [blk][plane][64][16]
            if (mma_on){
                float* gp = g_gp + ((size_t)blk*4 + nt)*1024;
                #pragma unroll
                for (int j = 0; j < 2; j++){
                    const int col = j*8 + 2*tig;
                    gp[(m0+g)*16 + col]       = aX[j][0];
                    gp[(m0+g)*16 + col + 1]   = aX[j][1];
                    gp[(m0+g+8)*16 + col]     = aX[j][2];
                    gp[(m0+g+8)*16 + col + 1] = aX[j][3];
                }
                if (nt == 2){
                    float* gp3 = g_gp + ((size_t)blk*4 + 3)*1024;
                    #pragma unroll
                    for (int j = 0; j < 2; j++){
                        const int col = j*8 + 2*tig;
                        gp3[(m0+g)*16 + col]       = aH[j][0];
                        gp3[(m0+g)*16 + col + 1]   = aH[j][1];
                        gp3[(m0+g+8)*16 + col]     = aH[j][2];
                        gp3[(m0+g+8)*16 + col + 1] = aH[j][3];
                    }
                }
            }
            // load Wd rows into smem (reuses A region)
            float* Wds = smf; float* hs = smf + 2048;
            {
                const int row = tid >> 6, c4 = (tid & 63)*4;
                *(float4*)(Wds + row*256 + c4) = *(const float4*)(Wd + (size_t)(blk*8+row)*AA + c4);
            }
        }
        psync(gen);   // pair partials visible
        // ---------- D: GRU pointwise + dp k-partials ----------
        {
            float* Wds = smf; float* hs = smf + 2048;
            {
                const int b = tid >> 3, dl = tid & 7, d = blk*8 + dl;
                const int cd = (blk & 1)*8 + dl;
                const int o = b*16 + cd;
                const float* gpA = g_gp + (size_t)(pair*2)*4096;
                const float* gpB = gpA + 4096;
                float gr  = gpA[o]        + gpB[o]        + bih[d]      + bhh[d];
                float gz  = gpA[1024 + o] + gpB[1024 + o] + bih[DD+d]   + bhh[DD+d];
                float gin = gpA[2048 + o] + gpB[2048 + o] + bih[2*DD+d];
                float ghn = gpA[3072 + o] + gpB[3072 + o] + bhh[2*DD+d];
                float r = fsig(gr), z = fsig(gz);
                float n = ftanh(gin + r*ghn);
                float h = g_h[b*DD + d];
                float hn = (1.f - z)*n + z*h;
                g_h[b*DD + d] = hn;
                g_Hb[((size_t)t*BB + b)*DD + d] = hn;
                __nv_bfloat16 hb = __float2bfloat16(hn);
                const int hoff = PP+EE + ((t+1)&1)*DD + d;
                g_Ah[b*KT2 + hoff] = hb;
                g_Al[b*KT2 + hoff] = __float2bfloat16(hn - __bfloat162float(hb));
                hs[b*8 + dl] = hn;
            }
            __syncthreads();
            {
                const int bg = tid >> 5, ag = tid & 31;
                const int b4 = bg*4, a8 = ag*8;
                float acc[4][8] = {};
                #pragma unroll
                for (int kk = 0; kk < 8; kk++){
                    const float4 w0 = *(const float4*)(Wds + kk*256 + a8);
                    const float4 w1 = *(const float4*)(Wds + kk*256 + a8 + 4);
                    #pragma unroll
                    for (int i = 0; i < 4; i++){
                        const float h = hs[(b4+i)*8 + kk];
                        acc[i][0]+=h*w0.x; acc[i][1]+=h*w0.y; acc[i][2]+=h*w0.z; acc[i][3]+=h*w0.w;
                        acc[i][4]+=h*w1.x; acc[i][5]+=h*w1.y; acc[i][6]+=h*w1.z; acc[i][7]+=h*w1.w;
                    }
                }
                #pragma unroll
                for (int i = 0; i < 4; i++){
                    float* o = g_dpp + ((size_t)(b4+i)*NB + blk)*AA + a8;
                    *(float4*)(o)   = make_float4(acc[i][0],acc[i][1],acc[i][2],acc[i][3]);
                    *(float4*)(o+4) = make_float4(acc[i][4],acc[i][5],acc[i][6],acc[i][7]);
                }
            }
        }
        gsync(gen);
    }
}

// ---------------- host ----------------
extern "C" void kernel_launch(void* const* d_in, const int* in_sizes, int n_in,
                              void* d_out, int out_size){
    const float* enc = (const float*)d_in[0];
    const float* tm  = (const float*)d_in[1];
    const float* We  = (const float*)d_in[2];
    const float* be  = (const float*)d_in[3];
    const float* Wd  = (const float*)d_in[4];
    const float* bd  = (const float*)d_in[5];
    const float* v   = (const float*)d_in[6];
    const float* bv  = (const float*)d_in[7];
    const float* W1  = (const float*)d_in[8];
    const float* b1  = (const float*)d_in[9];
    const float* W2  = (const float*)d_in[10];
    const float* b2  = (const float*)d_in[11];
    const float* Wih = (const float*)d_in[12];
    const float* bih = (const float*)d_in[13];
    const float* Whh = (const float*)d_in[14];
    const float* bhh = (const float*)d_in[15];
    const float* Wo  = (const float*)d_in[16];
    const float* bo  = (const float*)d_in[17];
    const float* Ws  = (const float*)d_in[18];
    const float* bs  = (const float*)d_in[19];
    float* out = (float*)d_out;

    float *p_prev, *p_ph, *p_pre, *p_Hb, *p_Cb; __half *p_epH;
    cudaGetSymbolAddress((void**)&p_epH,  g_epH);
    cudaGetSymbolAddress((void**)&p_prev, g_prev);
    cudaGetSymbolAddress((void**)&p_ph,   g_ph);
    cudaGetSymbolAddress((void**)&p_pre,  g_pre);
    cudaGetSymbolAddress((void**)&p_Hb,   g_Hb);
    cudaGetSymbolAddress((void**)&p_Cb,   g_Cb);

    cudaFuncSetAttribute(decode, cudaFuncAttributeMaxDynamicSharedMemorySize, 61440);

    // precompute
    k_init<<<(BB*NB*AA + 255)/256, 256>>>();
    k_prev<<<(TT*BB*MM + 255)/256, 256>>>(tm);
    k_convE<<<(BB*SS*EE + 255)/256, 256>>>(enc);
    k_pack<<<(64*NCHT*WBLOB + 255)/256, 256>>>(Wih, Whh);
    sgemm<<<dim3(HP/64, (TT*BB)/64), 256>>>(p_prev, W1, b1, p_ph,  TT*BB, HP, MM, 1, 0, 0);
    sgemm<<<dim3(PP/64, (TT*BB)/64), 256>>>(p_ph,   W2, b2, p_pre, TT*BB, PP, HP, 1, 0, 0);
    sgemm<<<dim3(AA/64, (BB*SS)/64), 256>>>(enc,    We, be, (float*)p_epH, BB*SS, AA, EE, 4, 0, 0);

    // sequential decode: one persistent kernel
    decode<<<NB, TPB, 61440>>>(Wd, bd, v, bv, bih, bhh, out);

    // output heads
    sgemm<<<dim3(MM/64, (TT*BB)/64), 256>>>(p_Hb, Wo,           bo,      out, TT*BB, MM, DD, 0, BB, TT);
    sgemm<<<dim3(MM/64, (TT*BB)/64), 256>>>(p_Cb, Wo + DD*MM,   nullptr, out, TT*BB, MM, EE, 2, BB, TT);
    k_stop<<<(TT*BB)/8, 256>>>(Ws, bs, out);
}

// round 9
// speedup vs baseline: 1.3213x; 1.0061x over previous
#include <cuda_runtime.h>
#include <cuda_bf16.h>
#include <cuda_fp16.h>

#define BB 64
#define SS 512
#define EE 512
#define AA 256
#define HP 256
#define PP 128
#define DD 1024
#define MM 128
#define TT 800
#define G3 3072
#define NB 128
#define TPB 512
#define KT2 2688
#define NCHT 26
#define WBLOB 1536

// smem word offsets
#define O_AB0 0
#define O_AB1 4608
#define O_WB0 9216
#define O_WB1 12288
#define O_DPS 15360
#define O_VS  15616
#define O_AWS 15872
#define O_ATTR 16384
#define O_SM2 16448
#define O_WDS 17472
#define O_HS  19520
#define SMEM_WORDS 20032

// ---------------- static scratch ----------------
__device__ __align__(128) __half g_epH[BB*SS*AA];
__device__ __align__(128) __half g_encH[BB*SS*EE];
__device__ __align__(128) float g_prev[TT*BB*MM];
__device__ __align__(128) float g_ph  [TT*BB*HP];
__device__ __align__(128) float g_pre [TT*BB*PP];
__device__ __align__(128) float g_h   [BB*DD];
__device__ __align__(128) float g_sc  [BB*SS];
__device__ __align__(128) float g_dpp [BB*NB*AA];
__device__ __align__(128) __nv_bfloat16 g_Ah[BB*KT2];
__device__ __align__(128) __nv_bfloat16 g_Al[BB*KT2];
__device__ __align__(128) uint2 g_Wf2[(size_t)64*NCHT*WBLOB];
__device__ __align__(128) float g_gp  [NB*4*64*16];
__device__ __align__(128) float g_Hb  [(size_t)TT*BB*DD];
__device__ __align__(128) float g_Cb  [(size_t)TT*BB*EE];
__device__ __align__(128) volatile unsigned g_flags[NB*32];
__device__ __align__(128) volatile unsigned g_pairf[NB*32];
__device__ __align__(128) volatile unsigned g_attf[NB*32];
__device__ volatile unsigned g_rel;

__device__ __forceinline__ float fsig(float x){
    float e = __expf(-x);
    return __fdividef(1.f, 1.f + e);
}
__device__ __forceinline__ float ftanh(float x){
    x = fminf(fmaxf(x, -15.f), 15.f);
    float e = __expf(2.f*x);
    return __fdividef(e - 1.f, e + 1.f);
}
__device__ __forceinline__ float tanh_mufu(float x){
    float y; asm("tanh.approx.f32 %0, %1;" : "=f"(y) : "f"(x)); return y;
}

__device__ __forceinline__ void gsync(unsigned &gen){
    gen++;
    __syncthreads();
    const int tid = threadIdx.x;
    if (blockIdx.x == 0){
        if (tid > 0 && tid < NB){
            while (g_flags[tid*32] < gen) {}
        }
        __syncthreads();
        if (tid == 0){ __threadfence(); g_rel = gen; }
    } else {
        if (tid == 0){
            __threadfence();
            g_flags[blockIdx.x*32] = gen;
            while (g_rel < gen) {}
            __threadfence();
        }
    }
    __syncthreads();
}

__device__ __forceinline__ void psync(unsigned &gen){
    gen++;
    __syncthreads();
    if (threadIdx.x == 0){
        __threadfence();
        g_pairf[blockIdx.x*32] = gen;
        while (g_pairf[(blockIdx.x^1)*32] < gen) {}
        __threadfence();
    }
    __syncthreads();
}

#define BAR1 asm volatile("bar.sync 1, 128;" ::: "memory")
#define BAR2 asm volatile("bar.sync 2, 384;" ::: "memory")

#define MMA(D0,D1,D2,D3,A0,A1,A2,A3,B0,B1) \
    asm volatile("mma.sync.aligned.m16n8k16.row.col.f32.bf16.bf16.f32 " \
        "{%0,%1,%2,%3},{%4,%5,%6,%7},{%8,%9},{%0,%1,%2,%3};" \
        : "+f"(D0),"+f"(D1),"+f"(D2),"+f"(D3) \
        : "r"(A0),"r"(A1),"r"(A2),"r"(A3),"r"(B0),"r"(B1))

// ---------------- generic tiled SGEMM (pre/epilogue only) ----------------
#define BKK 16
__global__ void sgemm(const float* __restrict__ A, const float* __restrict__ B,
                      const float* __restrict__ bias, float* __restrict__ C,
                      int M, int N, int K, int flags, int Bdim, int Tdim)
{
    __shared__ float As[BKK][64];
    __shared__ float Bs[BKK][64];
    const int n0 = blockIdx.x * 64;
    const int m0 = blockIdx.y * 64;
    const int tid = threadIdx.x;
    const int tx = tid & 15;
    const int ty = tid >> 4;
    float acc[4][4] = {};
    const int arow  = tid >> 2;
    const int acol4 = (tid & 3) * 4;
    const int brow  = tid >> 4;
    const int bcol4 = (tid & 15) * 4;

    for (int k = 0; k < K; k += BKK) {
        float4 av = *(const float4*)(A + (size_t)(m0 + arow) * K + k + acol4);
        As[acol4+0][arow] = av.x;
        As[acol4+1][arow] = av.y;
        As[acol4+2][arow] = av.z;
        As[acol4+3][arow] = av.w;
        float4 bvv = *(const float4*)(B + (size_t)(k + brow) * N + n0 + bcol4);
        *(float4*)(&Bs[brow][bcol4]) = bvv;
        __syncthreads();
        #pragma unroll
        for (int kk = 0; kk < BKK; kk++) {
            float4 a4 = *(const float4*)(&As[kk][ty*4]);
            float4 b4 = *(const float4*)(&Bs[kk][tx*4]);
            acc[0][0] += a4.x*b4.x; acc[0][1] += a4.x*b4.y; acc[0][2] += a4.x*b4.z; acc[0][3] += a4.x*b4.w;
            acc[1][0] += a4.y*b4.x; acc[1][1] += a4.y*b4.y; acc[1][2] += a4.y*b4.z; acc[1][3] += a4.y*b4.w;
            acc[2][0] += a4.z*b4.x; acc[2][1] += a4.z*b4.y; acc[2][2] += a4.z*b4.z; acc[2][3] += a4.z*b4.w;
            acc[3][0] += a4.w*b4.x; acc[3][1] += a4.w*b4.y; acc[3][2] += a4.w*b4.z; acc[3][3] += a4.w*b4.w;
        }
        __syncthreads();
    }
    #pragma unroll
    for (int i = 0; i < 4; i++) {
        const int m = m0 + ty*4 + i;
        #pragma unroll
        for (int j = 0; j < 4; j++) {
            const int n = n0 + tx*4 + j;
            float val = acc[i][j];
            if (bias) val += bias[n];
            if (flags & 1) val = fmaxf(val, 0.f);
            size_t idx;
            if (Bdim > 0) {
                const int bq = m % Bdim, tq = m / Bdim;
                idx = ((size_t)bq * Tdim + tq) * N + n;
            } else {
                idx = (size_t)m * N + n;
            }
            if (flags & 4)      ((__half*)C)[idx] = __float2half_rn(val);
            else if (flags & 2) C[idx] += val;
            else                C[idx] = val;
        }
    }
}

__global__ void k_init(){
    int i = blockIdx.x*256 + threadIdx.x;
    if (i < BB*NB*AA) g_dpp[i] = 0.f;
    if (i < BB*KT2){ g_Ah[i] = __float2bfloat16(0.f); g_Al[i] = __float2bfloat16(0.f); }
    if (i < BB*DD) g_h[i] = 0.f;
}

__global__ void k_prev(const float* __restrict__ tm){
    int i = blockIdx.x*256 + threadIdx.x;
    if (i >= TT*BB*MM) return;
    int m  = i & (MM-1);
    int tb = i >> 7;
    int b  = tb & (BB-1);
    int t  = tb >> 6;
    g_prev[i] = (t == 0) ? 0.f : tm[((size_t)b*TT + (t-1))*MM + m];
}

__global__ void k_convE(const float* __restrict__ enc){
    int i = blockIdx.x*256 + threadIdx.x;
    if (i < BB*SS*EE) g_encH[i] = __float2half_rn(enc[i]);
}

// pack [Wih; Whh] into per-(pair,chunk) contiguous blobs of mma B-fragments (bf16 hi/lo)
__global__ void k_pack(const float* __restrict__ Wih, const float* __restrict__ Whh){
    int id = blockIdx.x*256 + threadIdx.x;
    const int TOTW = 64*NCHT*WBLOB;
    if (id >= TOTW) return;
    const int lane = id & 31;
    const int hl   = (id >> 5) & 1;
    const int kl   = (id >> 6) & 3;
    const int j    = (id >> 8) & 1;
    const int idx2 = id % WBLOB;
    const int nt   = idx2 >> 9;
    const int c    = (id / WBLOB) % NCHT;
    const int pair = id / (WBLOB*NCHT);
    const int tig = lane & 3;
    const int n = nt*DD + pair*16 + j*8 + (lane >> 2);
    const int k0 = c*64 + kl*16;
    int kk[4] = {k0+2*tig, k0+2*tig+1, k0+8+2*tig, k0+9+2*tig};
    unsigned q[4];
    #pragma unroll
    for (int i2=0;i2<4;i2++){
        int k = kk[i2];
        float w = (k < PP+EE) ? Wih[(size_t)k*G3 + n] : Whh[(size_t)(k-(PP+EE))*G3 + n];
        __nv_bfloat16 hb = __float2bfloat16(w);
        if (hl){
            __nv_bfloat16 lb = __float2bfloat16(w - __bfloat162float(hb));
            q[i2] = *(unsigned short*)&lb;
        } else {
            q[i2] = *(unsigned short*)&hb;
        }
    }
    g_Wf2[id] = make_uint2((q[1]<<16)|q[0], (q[3]<<16)|q[2]);
}

__global__ void k_stop(const float* __restrict__ Ws, const float* __restrict__ bs,
                       float* __restrict__ dout){
    const int w = (blockIdx.x*blockDim.x + threadIdx.x) >> 5;
    const int lane = threadIdx.x & 31;
    if (w >= TT*BB) return;
    const float* hrow = g_Hb + (size_t)w*DD;
    const float* crow = g_Cb + (size_t)w*EE;
    float acc = 0.f;
    for (int k = lane; k < DD; k += 32) acc += hrow[k]*Ws[k];
    for (int k = lane; k < EE; k += 32) acc += crow[k]*Ws[DD+k];
    #pragma unroll
    for (int o = 16; o > 0; o >>= 1) acc += __shfl_down_sync(0xffffffffu, acc, o);
    if (lane == 0){
        const int tq = w / BB, bq = w % BB;
        dout[(size_t)BB*TT*MM + (size_t)bq*TT + tq] = acc + bs[0];
    }
}

// ================= persistent decode kernel =================
__global__ void __launch_bounds__(TPB)
decode(const float* __restrict__ Wd,  const float* __restrict__ bd,
       const float* __restrict__ v,   const float* __restrict__ bv,
       const float* __restrict__ bih, const float* __restrict__ bhh,
       float* __restrict__ out)
{
    extern __shared__ float smf[];
    unsigned* smu = (unsigned*)smf;
    const int blk = blockIdx.x, tid = threadIdx.x;
    const int lane = tid & 31, wq = tid >> 5;
    unsigned gen = g_rel;
    unsigned attGen = gen;

    const int pair = blk >> 1, ks = blk & 1;
    const uint2* Wsrc = g_Wf2 + (size_t)pair*NCHT*WBLOB;

    // MMA-warp geometry
    const int g = lane >> 2, tig = lane & 3;
    const int nt = wq >> 2;
    const int m0 = (wq & 3) * 16;

    for (int t = 0; t < TT; t++){
        const int par = t & 1;
        float aX[2][4] = {}, aH[2][4] = {};
        // ---------- phase 0 (all threads): dp partial reduce ----------
        {
            float* part = smf + O_AWS;
            const int a = tid & 255, jh = tid >> 8;
            const float* pp = g_dpp + ((size_t)pair*NB + jh*64)*AA + a;
            float s = 0.f;
            #pragma unroll 16
            for (int j = 0; j < 64; j++) s += pp[(size_t)j*AA];
            part[tid] = s;
            __syncthreads();
            if (tid < 256){
                smf[O_DPS + tid] = part[tid] + part[256+tid] + bd[tid];
                smf[O_VS  + tid] = v[tid];
            }
            __syncthreads();
        }
        // ---------- phase 1: concurrent [Ch MMA | attention] ----------
        if (wq < 12){
            // ----- h-part gates GEMM: 8 chunks (global chunks 10+ks*8 .. +8) -----
            const int t384 = tid;
            {
                const int c = 10 + ks*8;
                const int idx4 = 80 + (c-10)*8 + par*128;
                for (int idx = t384; idx < 512; idx += 384){
                    const int row = idx >> 3, col = idx & 7;
                    ((uint4*)(smu+O_AB0))[row*9+col]        = ((const uint4*)g_Ah)[row*336 + idx4 + col];
                    ((uint4*)(smu+O_AB0+2304))[row*9+col]   = ((const uint4*)g_Al)[row*336 + idx4 + col];
                }
                uint2* wb = (uint2*)(smu + O_WB0);
                const uint2* src = Wsrc + (size_t)c*WBLOB;
                wb[t384] = src[t384]; wb[t384+384] = src[t384+384];
                wb[t384+768] = src[t384+768]; wb[t384+1152] = src[t384+1152];
            }
            BAR2;
            for (int i = 0; i < 8; i++){
                uint4 nah0, nal0, nah1, nal1; uint2 nw0, nw1, nw2, nw3;
                const bool pf = (i < 7);
                if (pf){
                    const int c = 10 + ks*8 + i + 1;
                    const int idx4 = 80 + (c-10)*8 + par*128;
                    if (t384 < 256){
                        const int r0i = t384 >> 3, c0i = t384 & 7;
                        nah0 = ((const uint4*)g_Ah)[r0i*336 + idx4 + c0i];
                        nal0 = ((const uint4*)g_Al)[r0i*336 + idx4 + c0i];
                        const int i2 = t384 + 256;
                        const int r1i = i2 >> 3, c1i = i2 & 7;
                        nah1 = ((const uint4*)g_Ah)[r1i*336 + idx4 + c1i];
                        nal1 = ((const uint4*)g_Al)[r1i*336 + idx4 + c1i];
                    }
                    const uint2* src = Wsrc + (size_t)c*WBLOB;
                    nw0 = src[t384]; nw1 = src[t384+384];
                    nw2 = src[t384+768]; nw3 = src[t384+1152];
                }
                {
                    const unsigned* Ah32 = smu + O_AB0 + (i&1)*4608;
                    const unsigned* Al32 = Ah32 + 2304;
                    const uint2* Wq = (const uint2*)(smu + O_WB0 + (i&1)*3072) + nt*512;
                    #pragma unroll
                    for (int kl = 0; kl < 4; kl++){
                        const int r0 = (m0+g)*36 + kl*8 + tig;
                        unsigned a0 = Ah32[r0],   a1 = Ah32[r0+288];
                        unsigned a2 = Ah32[r0+4], a3 = Ah32[r0+292];
                        unsigned l0 = Al32[r0],   l1 = Al32[r0+288];
                        unsigned l2 = Al32[r0+4], l3 = Al32[r0+292];
                        #pragma unroll
                        for (int j = 0; j < 2; j++){
                            uint2 bh = Wq[j*256 + kl*64 + lane];
                            uint2 bl = Wq[j*256 + kl*64 + 32 + lane];
                            if (nt == 2){
                                MMA(aH[j][0],aH[j][1],aH[j][2],aH[j][3], a0,a1,a2,a3, bh.x,bh.y);
                                MMA(aH[j][0],aH[j][1],aH[j][2],aH[j][3], a0,a1,a2,a3, bl.x,bl.y);
                                MMA(aH[j][0],aH[j][1],aH[j][2],aH[j][3], l0,l1,l2,l3, bh.x,bh.y);
                            } else {
                                MMA(aX[j][0],aX[j][1],aX[j][2],aX[j][3], a0,a1,a2,a3, bh.x,bh.y);
                                MMA(aX[j][0],aX[j][1],aX[j][2],aX[j][3], a0,a1,a2,a3, bl.x,bl.y);
                                MMA(aX[j][0],aX[j][1],aX[j][2],aX[j][3], l0,l1,l2,l3, bh.x,bh.y);
                            }
                        }
                    }
                }
                if (pf){
                    unsigned* bufA = smu + O_AB0 + ((i+1)&1)*4608;
                    if (t384 < 256){
                        const int r0i = t384 >> 3, c0i = t384 & 7;
                        ((uint4*)bufA)[r0i*9+c0i] = nah0;
                        ((uint4*)(bufA+2304))[r0i*9+c0i] = nal0;
                        const int i2 = t384 + 256;
                        ((uint4*)bufA)[(i2>>3)*9+(i2&7)] = nah1;
                        ((uint4*)(bufA+2304))[(i2>>3)*9+(i2&7)] = nal1;
                    }
                    uint2* wb = (uint2*)(smu + O_WB0 + ((i+1)&1)*3072);
                    wb[t384]=nw0; wb[t384+384]=nw1; wb[t384+768]=nw2; wb[t384+1152]=nw3;
                }
                BAR2;
            }
        } else {
            // ----- attention: scores -> pair sync -> softmax -> context -----
            const int tl = tid - 384;
            const float bv0 = bv[0];
            const float* dps = smf + O_DPS;
            const float* vs  = smf + O_VS;
            #pragma unroll
            for (int rep = 0; rep < 2; rep++){
                const int s = ks*256 + rep*128 + tl;
                const uint4* ep4 = (const uint4*)(g_epH + ((size_t)(pair*SS + s))*AA);
                float acc = 0.f;
                #pragma unroll 8
                for (int q = 0; q < 32; q++){
                    uint4 u = ep4[q];
                    float2 f0 = __half22float2(*(__half2*)&u.x);
                    float2 f1 = __half22float2(*(__half2*)&u.y);
                    float2 f2 = __half22float2(*(__half2*)&u.z);
                    float2 f3 = __half22float2(*(__half2*)&u.w);
                    const int i0 = q*8;
                    acc += vs[i0+0]*tanh_mufu(f0.x + dps[i0+0]);
                    acc += vs[i0+1]*tanh_mufu(f0.y + dps[i0+1]);
                    acc += vs[i0+2]*tanh_mufu(f1.x + dps[i0+2]);
                    acc += vs[i0+3]*tanh_mufu(f1.y + dps[i0+3]);
                    acc += vs[i0+4]*tanh_mufu(f2.x + dps[i0+4]);
                    acc += vs[i0+5]*tanh_mufu(f2.y + dps[i0+5]);
                    acc += vs[i0+6]*tanh_mufu(f3.x + dps[i0+6]);
                    acc += vs[i0+7]*tanh_mufu(f3.y + dps[i0+7]);
                }
                g_sc[pair*SS + s] = acc + bv0;
            }
            // pair sync (attention warps only)
            attGen++;
            BAR1;
            if (tl == 0){
                __threadfence();
                g_attf[blk*32] = attGen;
                while (g_attf[(blk^1)*32] < attGen) {}
                __threadfence();
            }
            BAR1;
            // softmax over full 512
            float* attr = smf + O_ATTR;
            float4 sc4 = *(const float4*)(g_sc + pair*SS + tl*4);
            float mx = fmaxf(fmaxf(sc4.x, sc4.y), fmaxf(sc4.z, sc4.w));
            #pragma unroll
            for (int o = 16; o; o >>= 1) mx = fmaxf(mx, __shfl_xor_sync(0xffffffffu, mx, o));
            if (lane == 0) attr[wq-12] = mx;
            BAR1;
            mx = fmaxf(fmaxf(attr[0], attr[1]), fmaxf(attr[2], attr[3]));
            float e0 = __expf(sc4.x - mx), e1 = __expf(sc4.y - mx);
            float e2 = __expf(sc4.z - mx), e3 = __expf(sc4.w - mx);
            float ss = e0 + e1 + e2 + e3;
            #pragma unroll
            for (int o = 16; o; o >>= 1) ss += __shfl_xor_sync(0xffffffffu, ss, o);
            if (lane == 0) attr[4 + (wq-12)] = ss;
            BAR1;
            const float inv = __fdividef(1.f, attr[4]+attr[5]+attr[6]+attr[7]);
            float4 av4 = make_float4(e0*inv, e1*inv, e2*inv, e3*inv);
            *(float4*)(smf + O_AWS + tl*4) = av4;
            if (ks == 0){
                *(float4*)(out + (size_t)BB*TT*MM + (size_t)BB*TT + ((size_t)pair*TT + t)*SS + tl*4) = av4;
                // stage prenet for this step (x-chunk cols 0..127)
                float pv = g_pre[((size_t)t*BB + pair)*PP + tl];
                __nv_bfloat16 hb = __float2bfloat16(pv);
                g_Ah[pair*KT2 + tl] = hb;
                g_Al[pair*KT2 + tl] = __float2bfloat16(pv - __bfloat162float(hb));
            }
            BAR1;
            // context: thread = (s-quarter, col-octet) over this block's eh=ks half
            const int ec = tl & 31, sq = tl >> 5;
            const uint4* eb = (const uint4*)(g_encH + ((size_t)(pair*SS + sq*128))*EE + ks*256) + ec;
            const float* awq = smf + O_AWS + sq*128;
            float c[8] = {};
            #pragma unroll 8
            for (int s2 = 0; s2 < 128; s2++){
                uint4 u = eb[(size_t)s2*64];
                float a = awq[s2];
                float2 q0 = __half22float2(*(__half2*)&u.x);
                float2 q1 = __half22float2(*(__half2*)&u.y);
                float2 q2 = __half22float2(*(__half2*)&u.z);
                float2 q3 = __half22float2(*(__half2*)&u.w);
                c[0]+=a*q0.x; c[1]+=a*q0.y; c[2]+=a*q1.x; c[3]+=a*q1.y;
                c[4]+=a*q2.x; c[5]+=a*q2.y; c[6]+=a*q3.x; c[7]+=a*q3.y;
            }
            float* sm2 = smf + O_SM2;
            #pragma unroll
            for (int k = 0; k < 8; k++) sm2[sq*256 + ec*8 + k] = c[k];
            BAR1;
            #pragma unroll
            for (int r = 0; r < 2; r++){
                const int col = tl*2 + r;
                float cc = sm2[col] + sm2[256+col] + sm2[512+col] + sm2[768+col];
                const int e2i = ks*256 + col;
                g_Cb[((size_t)t*BB + pair)*EE + e2i] = cc;
                __nv_bfloat16 hb = __float2bfloat16(cc);
                g_Ah[pair*KT2 + PP + e2i] = hb;
                g_Al[pair*KT2 + PP + e2i] = __float2bfloat16(cc - __bfloat162float(hb));
            }
        }
        gsync(gen);
        // ---------- phase 2: x-part gates GEMM (5 chunks) | Wd preload ----------
        if (wq < 12){
            const int t384 = tid;
            {
                const int c = ks*5;
                const int idx4 = c*8;
                for (int idx = t384; idx < 512; idx += 384){
                    const int row = idx >> 3, col = idx & 7;
                    ((uint4*)(smu+O_AB0))[row*9+col]      = ((const uint4*)g_Ah)[row*336 + idx4 + col];
                    ((uint4*)(smu+O_AB0+2304))[row*9+col] = ((const uint4*)g_Al)[row*336 + idx4 + col];
                }
                uint2* wb = (uint2*)(smu + O_WB0);
                const uint2* src = Wsrc + (size_t)c*WBLOB;
                wb[t384] = src[t384]; wb[t384+384] = src[t384+384];
                wb[t384+768] = src[t384+768]; wb[t384+1152] = src[t384+1152];
            }
            BAR2;
            for (int i = 0; i < 5; i++){
                uint4 nah0, nal0, nah1, nal1; uint2 nw0, nw1, nw2, nw3;
                const bool pf = (i < 4);
                if (pf){
                    const int c = ks*5 + i + 1;
                    const int idx4 = c*8;
                    if (t384 < 256){
                        const int r0i = t384 >> 3, c0i = t384 & 7;
                        nah0 = ((const uint4*)g_Ah)[r0i*336 + idx4 + c0i];
                        nal0 = ((const uint4*)g_Al)[r0i*336 + idx4 + c0i];
                        const int i2 = t384 + 256;
                        const int r1i = i2 >> 3, c1i = i2 & 7;
                        nah1 = ((const uint4*)g_Ah)[r1i*336 + idx4 + c1i];
                        nal1 = ((const uint4*)g_Al)[r1i*336 + idx4 + c1i];
                    }
                    const uint2* src = Wsrc + (size_t)c*WBLOB;
                    nw0 = src[t384]; nw1 = src[t384+384];
                    nw2 = src[t384+768]; nw3 = src[t384+1152];
                }
                {
                    const unsigned* Ah32 = smu + O_AB0 + (i&1)*4608;
                    const unsigned* Al32 = Ah32 + 2304;
                    const uint2* Wq = (const uint2*)(smu + O_WB0 + (i&1)*3072) + nt*512;
                    #pragma unroll
                    for (int kl = 0; kl < 4; kl++){
                        const int r0 = (m0+g)*36 + kl*8 + tig;
                        unsigned a0 = Ah32[r0],   a1 = Ah32[r0+288];
                        unsigned a2 = Ah32[r0+4], a3 = Ah32[r0+292];
                        unsigned l0 = Al32[r0],   l1 = Al32[r0+288];
                        unsigned l2 = Al32[r0+4], l3 = Al32[r0+292];
                        #pragma unroll
                        for (int j = 0; j < 2; j++){
                            uint2 bh = Wq[j*256 + kl*64 + lane];
                            uint2 bl = Wq[j*256 + kl*64 + 32 + lane];
                            MMA(aX[j][0],aX[j][1],aX[j][2],aX[j][3], a0,a1,a2,a3, bh.x,bh.y);
                            MMA(aX[j][0],aX[j][1],aX[j][2],aX[j][3], a0,a1,a2,a3, bl.x,bl.y);
                            MMA(aX[j][0],aX[j][1],aX[j][2],aX[j][3], l0,l1,l2,l3, bh.x,bh.y);
                        }
                    }
                }
                if (pf){
                    unsigned* bufA = smu + O_AB0 + ((i+1)&1)*4608;
                    if (t384 < 256){
                        const int r0i = t384 >> 3, c0i = t384 & 7;
                        ((uint4*)bufA)[r0i*9+c0i] = nah0;
                        ((uint4*)(bufA+2304))[r0i*9+c0i] = nal0;
                        const int i2 = t384 + 256;
                        ((uint4*)bufA)[(i2>>3)*9+(i2&7)] = nah1;
                        ((uint4*)(bufA+2304))[(i2>>3)*9+(i2&7)] = nal1;
                    }
                    uint2* wb = (uint2*)(smu + O_WB0 + ((i+1)&1)*3072);
                    wb[t384]=nw0; wb[t384+384]=nw1; wb[t384+768]=nw2; wb[t384+1152]=nw3;
                }
                BAR2;
            }
            // write gate partials [blk][plane][64][16]
            {
                float* gp = g_gp + ((size_t)blk*4 + nt)*1024;
                #pragma unroll
                for (int j = 0; j < 2; j++){
                    const int col = j*8 + 2*tig;
                    gp[(m0+g)*16 + col]       = aX[j][0];
                    gp[(m0+g)*16 + col + 1]   = aX[j][1];
                    gp[(m0+g+8)*16 + col]     = aX[j][2];
                    gp[(m0+g+8)*16 + col + 1] = aX[j][3];
                }
                if (nt == 2){
                    float* gp3 = g_gp + ((size_t)blk*4 + 3)*1024;
                    #pragma unroll
                    for (int j = 0; j < 2; j++){
                        const int col = j*8 + 2*tig;
                        gp3[(m0+g)*16 + col]       = aH[j][0];
                        gp3[(m0+g)*16 + col + 1]   = aH[j][1];
                        gp3[(m0+g+8)*16 + col]     = aH[j][2];
                        gp3[(m0+g+8)*16 + col + 1] = aH[j][3];
                    }
                }
            }
        } else {
            // attention warps: preload Wd rows (blk*8..+8) into smem for phase D
            const int tl = tid - 384;
            for (int r = tl; r < 512; r += 128)
                ((float4*)(smf + O_WDS))[r] = ((const float4*)(Wd + (size_t)blk*8*AA))[r];
        }
        psync(gen);
        // ---------- phase D: GRU pointwise + dp k-partials ----------
        {
            float* Wds = smf + O_WDS; float* hs = smf + O_HS;
            {
                const int b = tid >> 3, dl = tid & 7, d = blk*8 + dl;
                const int cd = ks*8 + dl;
                const int o = b*16 + cd;
                const float* gpA = g_gp + (size_t)(pair*2)*4096;
                const float* gpB = gpA + 4096;
                float gr  = gpA[o]        + gpB[o]        + bih[d]      + bhh[d];
                float gz  = gpA[1024 + o] + gpB[1024 + o] + bih[DD+d]   + bhh[DD+d];
                float gin = gpA[2048 + o] + gpB[2048 + o] + bih[2*DD+d];
                float ghn = gpA[3072 + o] + gpB[3072 + o] + bhh[2*DD+d];
                float r = fsig(gr), z = fsig(gz);
                float n = ftanh(gin + r*ghn);
                float h = g_h[b*DD + d];
                float hn = (1.f - z)*n + z*h;
                g_h[b*DD + d] = hn;
                g_Hb[((size_t)t*BB + b)*DD + d] = hn;
                __nv_bfloat16 hb = __float2bfloat16(hn);
                const int hoff = PP+EE + ((t+1)&1)*DD + d;
                g_Ah[b*KT2 + hoff] = hb;
                g_Al[b*KT2 + hoff] = __float2bfloat16(hn - __bfloat162float(hb));
                hs[b*8 + dl] = hn;
            }
            __syncthreads();
            {
                const int bg = tid >> 5, ag = tid & 31;
                const int b4 = bg*4, a8 = ag*8;
                float acc[4][8] = {};
                #pragma unroll
                for (int kk = 0; kk < 8; kk++){
                    const float4 w0 = *(const float4*)(Wds + kk*256 + a8);
                    const float4 w1 = *(const float4*)(Wds + kk*256 + a8 + 4);
                    #pragma unroll
                    for (int i = 0; i < 4; i++){
                        const float h = hs[(b4+i)*8 + kk];
                        acc[i][0]+=h*w0.x; acc[i][1]+=h*w0.y; acc[i][2]+=h*w0.z; acc[i][3]+=h*w0.w;
                        acc[i][4]+=h*w1.x; acc[i][5]+=h*w1.y; acc[i][6]+=h*w1.z; acc[i][7]+=h*w1.w;
                    }
                }
                #pragma unroll
                for (int i = 0; i < 4; i++){
                    float* o = g_dpp + ((size_t)(b4+i)*NB + blk)*AA + a8;
                    *(float4*)(o)   = make_float4(acc[i][0],acc[i][1],acc[i][2],acc[i][3]);
                    *(float4*)(o+4) = make_float4(acc[i][4],acc[i][5],acc[i][6],acc[i][7]);
                }
            }
        }
        gsync(gen);
    }
}

// ---------------- host ----------------
extern "C" void kernel_launch(void* const* d_in, const int* in_sizes, int n_in,
                              void* d_out, int out_size){
    const float* enc = (const float*)d_in[0];
    const float* tm  = (const float*)d_in[1];
    const float* We  = (const float*)d_in[2];
    const float* be  = (const float*)d_in[3];
    const float* Wd  = (const float*)d_in[4];
    const float* bd  = (const float*)d_in[5];
    const float* v   = (const float*)d_in[6];
    const float* bv  = (const float*)d_in[7];
    const float* W1  = (const float*)d_in[8];
    const float* b1  = (const float*)d_in[9];
    const float* W2  = (const float*)d_in[10];
    const float* b2  = (const float*)d_in[11];
    const float* Wih = (const float*)d_in[12];
    const float* bih = (const float*)d_in[13];
    const float* Whh = (const float*)d_in[14];
    const float* bhh = (const float*)d_in[15];
    const float* Wo  = (const float*)d_in[16];
    const float* bo  = (const float*)d_in[17];
    const float* Ws  = (const float*)d_in[18];
    const float* bs  = (const float*)d_in[19];
    float* out = (float*)d_out;

    float *p_prev, *p_ph, *p_pre, *p_Hb, *p_Cb; __half *p_epH;
    cudaGetSymbolAddress((void**)&p_epH,  g_epH);
    cudaGetSymbolAddress((void**)&p_prev, g_prev);
    cudaGetSymbolAddress((void**)&p_ph,   g_ph);
    cudaGetSymbolAddress((void**)&p_pre,  g_pre);
    cudaGetSymbolAddress((void**)&p_Hb,   g_Hb);
    cudaGetSymbolAddress((void**)&p_Cb,   g_Cb);

    cudaFuncSetAttribute(decode, cudaFuncAttributeMaxDynamicSharedMemorySize, SMEM_WORDS*4);

    // precompute
    k_init<<<(BB*NB*AA + 255)/256, 256>>>();
    k_prev<<<(TT*BB*MM + 255)/256, 256>>>(tm);
    k_convE<<<(BB*SS*EE + 255)/256, 256>>>(enc);
    k_pack<<<(64*NCHT*WBLOB + 255)/256, 256>>>(Wih, Whh);
    sgemm<<<dim3(HP/64, (TT*BB)/64), 256>>>(p_prev, W1, b1, p_ph,  TT*BB, HP, MM, 1, 0, 0);
    sgemm<<<dim3(PP/64, (TT*BB)/64), 256>>>(p_ph,   W2, b2, p_pre, TT*BB, PP, HP, 1, 0, 0);
    sgemm<<<dim3(AA/64, (BB*SS)/64), 256>>>(enc,    We, be, (float*)p_epH, BB*SS, AA, EE, 4, 0, 0);

    // sequential decode: one persistent kernel
    decode<<<NB, TPB, SMEM_WORDS*4>>>(Wd, bd, v, bv, bih, bhh, out);

    // output heads
    sgemm<<<dim3(MM/64, (TT*BB)/64), 256>>>(p_Hb, Wo,           bo,      out, TT*BB, MM, DD, 0, BB, TT);
    sgemm<<<dim3(MM/64, (TT*BB)/64), 256>>>(p_Cb, Wo + DD*MM,   nullptr, out, TT*BB, MM, EE, 2, BB, TT);
    k_stop<<<(TT*BB)/8, 256>>>(Ws, bs, out);
}

// round 10
// speedup vs baseline: 1.6759x; 1.2684x over previous
#include <cuda_runtime.h>
#include <cuda_bf16.h>
#include <cuda_fp16.h>

#define BB 64
#define SS 512
#define EE 512
#define AA 256
#define HP 256
#define PP 128
#define DD 1024
#define MM 128
#define TT 800
#define G3 3072
#define NB 128
#define NBL 148
#define TPB 512
#define KT2 2688
#define NCHT 26
#define WBLOB 1536

// dynamic smem layout (float words)
#define SL_A(s) ((s)*4608)
#define SL_W(s) (13824 + (s)*3072)
#define O_DPS 23040
#define O_VS  23296
#define O_AWS 23552
#define O_ATTR 24064
#define O_SM2 24128
#define O_WDS 26176
#define O_HS  28224
#define SMEM_WORDS 28736

// ---------------- static scratch ----------------
__device__ __align__(128) __half g_epH[BB*SS*AA];
__device__ __align__(128) __half g_encH[BB*SS*EE];
__device__ __align__(128) float g_prev[TT*BB*MM];
__device__ __align__(128) float g_ph  [TT*BB*HP];
__device__ __align__(128) float g_pre [TT*BB*PP];
__device__ __align__(128) float g_h   [BB*DD];
__device__ __align__(128) float g_sc  [BB*SS];
__device__ __align__(128) float g_dpp [BB*NB*AA];
__device__ __align__(128) __nv_bfloat16 g_Ah[BB*KT2];
__device__ __align__(128) __nv_bfloat16 g_Al[BB*KT2];
__device__ __align__(128) uint2 g_Wf2[(size_t)64*NCHT*WBLOB];
__device__ __align__(128) float g_gp  [NB*4*64*16];
__device__ __align__(128) float g_Hb  [(size_t)TT*BB*DD];
__device__ __align__(128) float g_Cb  [(size_t)TT*BB*EE];
__device__ __align__(128) volatile unsigned g_flags[NBL*32];
__device__ __align__(128) volatile unsigned g_pairf[NBL*32];
__device__ __align__(128) volatile unsigned g_attf[NB*32];
__device__ volatile unsigned g_rel;

__device__ __forceinline__ float fsig(float x){
    float e = __expf(-x);
    return __fdividef(1.f, 1.f + e);
}
__device__ __forceinline__ float ftanh(float x){
    x = fminf(fmaxf(x, -15.f), 15.f);
    float e = __expf(2.f*x);
    return __fdividef(e - 1.f, e + 1.f);
}
__device__ __forceinline__ float tanh_mufu(float x){
    float y; asm("tanh.approx.f32 %0, %1;" : "=f"(y) : "f"(x)); return y;
}

__device__ __forceinline__ void gsync(unsigned &gen){
    gen++;
    __syncthreads();
    const int tid = threadIdx.x;
    if (blockIdx.x == 0){
        if (tid > 0 && tid < NBL){
            while (g_flags[tid*32] < gen) {}
        }
        __syncthreads();
        if (tid == 0){ __threadfence(); g_rel = gen; }
    } else {
        if (tid == 0){
            __threadfence();
            g_flags[blockIdx.x*32] = gen;
            while (g_rel < gen) {}
            __threadfence();
        }
    }
    __syncthreads();
}

__device__ __forceinline__ void psync(unsigned &gen){
    gen++;
    __syncthreads();
    if (threadIdx.x == 0){
        __threadfence();
        g_pairf[blockIdx.x*32] = gen;
        while (g_pairf[(blockIdx.x^1)*32] < gen) {}
        __threadfence();
    }
    __syncthreads();
}

#define BAR1 asm volatile("bar.sync 1, 128;" ::: "memory")
#define BAR2 asm volatile("bar.sync 2, 384;" ::: "memory")

__device__ __forceinline__ void cp16(unsigned dst, const void* src){
    asm volatile("cp.async.cg.shared.global [%0], [%1], 16;" :: "r"(dst), "l"(src) : "memory");
}
#define CP_COMMIT() asm volatile("cp.async.commit_group;" ::: "memory")
#define CP_WAIT2()  asm volatile("cp.async.wait_group 2;" ::: "memory")

#define MMA(D0,D1,D2,D3,A0,A1,A2,A3,B0,B1) \
    asm volatile("mma.sync.aligned.m16n8k16.row.col.f32.bf16.bf16.f32 " \
        "{%0,%1,%2,%3},{%4,%5,%6,%7},{%8,%9},{%0,%1,%2,%3};" \
        : "+f"(D0),"+f"(D1),"+f"(D2),"+f"(D3) \
        : "r"(A0),"r"(A1),"r"(A2),"r"(A3),"r"(B0),"r"(B1))

#define DO_MMA(ACC) { \
    const unsigned* Ah32 = smu + SL_A(slot); \
    const unsigned* Al32 = Ah32 + 2304; \
    const uint2* Wq = (const uint2*)(smu + SL_W(slot)) + nt*512; \
    _Pragma("unroll") \
    for (int kl = 0; kl < 4; kl++){ \
        const int r0 = (m0+g)*36 + kl*8 + tig; \
        unsigned a0 = Ah32[r0],   a1 = Ah32[r0+288]; \
        unsigned a2 = Ah32[r0+4], a3 = Ah32[r0+292]; \
        unsigned l0 = Al32[r0],   l1 = Al32[r0+288]; \
        unsigned l2 = Al32[r0+4], l3 = Al32[r0+292]; \
        _Pragma("unroll") \
        for (int j = 0; j < 2; j++){ \
            uint2 bh = Wq[j*256 + kl*64 + lane]; \
            uint2 bl = Wq[j*256 + kl*64 + 32 + lane]; \
            MMA(ACC[j][0],ACC[j][1],ACC[j][2],ACC[j][3], a0,a1,a2,a3, bh.x,bh.y); \
            MMA(ACC[j][0],ACC[j][1],ACC[j][2],ACC[j][3], a0,a1,a2,a3, bl.x,bl.y); \
            MMA(ACC[j][0],ACC[j][1],ACC[j][2],ACC[j][3], l0,l1,l2,l3, bh.x,bh.y); \
        } \
    } }

// stage one 64-col chunk (A hi/lo + W blob) into pipeline slot via cp.async
__device__ __forceinline__ void stage_chunk(unsigned sbase, int slot, int idx4,
                                            const uint2* wsrc_c, int tid){
    #pragma unroll
    for (int k = 0; k < 2; k++){
        int idx = tid + k*384;
        if (idx < 512){
            int row = idx >> 3, col = idx & 7;
            unsigned d = sbase + (SL_A(slot) + (row*9+col)*4)*4;
            cp16(d,          (const uint4*)g_Ah + row*336 + idx4 + col);
            cp16(d + 2304*4, (const uint4*)g_Al + row*336 + idx4 + col);
        }
    }
    const uint4* w4 = (const uint4*)wsrc_c;
    unsigned wd = sbase + SL_W(slot)*4;
    cp16(wd + (unsigned)tid*16,        w4 + tid);
    cp16(wd + (unsigned)(tid+384)*16,  w4 + tid + 384);
    CP_COMMIT();
}

// ---------------- generic tiled SGEMM (pre/epilogue only) ----------------
#define BKK 16
__global__ void sgemm(const float* __restrict__ A, const float* __restrict__ B,
                      const float* __restrict__ bias, float* __restrict__ C,
                      int M, int N, int K, int flags, int Bdim, int Tdim)
{
    __shared__ float As[BKK][64];
    __shared__ float Bs[BKK][64];
    const int n0 = blockIdx.x * 64;
    const int m0 = blockIdx.y * 64;
    const int tid = threadIdx.x;
    const int tx = tid & 15;
    const int ty = tid >> 4;
    float acc[4][4] = {};
    const int arow  = tid >> 2;
    const int acol4 = (tid & 3) * 4;
    const int brow  = tid >> 4;
    const int bcol4 = (tid & 15) * 4;

    for (int k = 0; k < K; k += BKK) {
        float4 av = *(const float4*)(A + (size_t)(m0 + arow) * K + k + acol4);
        As[acol4+0][arow] = av.x;
        As[acol4+1][arow] = av.y;
        As[acol4+2][arow] = av.z;
        As[acol4+3][arow] = av.w;
        float4 bvv = *(const float4*)(B + (size_t)(k + brow) * N + n0 + bcol4);
        *(float4*)(&Bs[brow][bcol4]) = bvv;
        __syncthreads();
        #pragma unroll
        for (int kk = 0; kk < BKK; kk++) {
            float4 a4 = *(const float4*)(&As[kk][ty*4]);
            float4 b4 = *(const float4*)(&Bs[kk][tx*4]);
            acc[0][0] += a4.x*b4.x; acc[0][1] += a4.x*b4.y; acc[0][2] += a4.x*b4.z; acc[0][3] += a4.x*b4.w;
            acc[1][0] += a4.y*b4.x; acc[1][1] += a4.y*b4.y; acc[1][2] += a4.y*b4.z; acc[1][3] += a4.y*b4.w;
            acc[2][0] += a4.z*b4.x; acc[2][1] += a4.z*b4.y; acc[2][2] += a4.z*b4.z; acc[2][3] += a4.z*b4.w;
            acc[3][0] += a4.w*b4.x; acc[3][1] += a4.w*b4.y; acc[3][2] += a4.w*b4.z; acc[3][3] += a4.w*b4.w;
        }
        __syncthreads();
    }
    #pragma unroll
    for (int i = 0; i < 4; i++) {
        const int m = m0 + ty*4 + i;
        #pragma unroll
        for (int j = 0; j < 4; j++) {
            const int n = n0 + tx*4 + j;
            float val = acc[i][j];
            if (bias) val += bias[n];
            if (flags & 1) val = fmaxf(val, 0.f);
            size_t idx;
            if (Bdim > 0) {
                const int bq = m % Bdim, tq = m / Bdim;
                idx = ((size_t)bq * Tdim + tq) * N + n;
            } else {
                idx = (size_t)m * N + n;
            }
            if (flags & 4)      ((__half*)C)[idx] = __float2half_rn(val);
            else if (flags & 2) C[idx] += val;
            else                C[idx] = val;
        }
    }
}

__global__ void k_init(){
    int i = blockIdx.x*256 + threadIdx.x;
    if (i < BB*NB*AA) g_dpp[i] = 0.f;
    if (i < BB*KT2){ g_Ah[i] = __float2bfloat16(0.f); g_Al[i] = __float2bfloat16(0.f); }
    if (i < BB*DD) g_h[i] = 0.f;
}

__global__ void k_prev(const float* __restrict__ tm){
    int i = blockIdx.x*256 + threadIdx.x;
    if (i >= TT*BB*MM) return;
    int m  = i & (MM-1);
    int tb = i >> 7;
    int b  = tb & (BB-1);
    int t  = tb >> 6;
    g_prev[i] = (t == 0) ? 0.f : tm[((size_t)b*TT + (t-1))*MM + m];
}

__global__ void k_convE(const float* __restrict__ enc){
    int i = blockIdx.x*256 + threadIdx.x;
    if (i < BB*SS*EE) g_encH[i] = __float2half_rn(enc[i]);
}

__global__ void k_pack(const float* __restrict__ Wih, const float* __restrict__ Whh){
    int id = blockIdx.x*256 + threadIdx.x;
    const int TOTW = 64*NCHT*WBLOB;
    if (id >= TOTW) return;
    const int lane = id & 31;
    const int hl   = (id >> 5) & 1;
    const int kl   = (id >> 6) & 3;
    const int j    = (id >> 8) & 1;
    const int idx2 = id % WBLOB;
    const int nt   = idx2 >> 9;
    const int c    = (id / WBLOB) % NCHT;
    const int pair = id / (WBLOB*NCHT);
    const int tig = lane & 3;
    const int n = nt*DD + pair*16 + j*8 + (lane >> 2);
    const int k0 = c*64 + kl*16;
    int kk[4] = {k0+2*tig, k0+2*tig+1, k0+8+2*tig, k0+9+2*tig};
    unsigned q[4];
    #pragma unroll
    for (int i2=0;i2<4;i2++){
        int k = kk[i2];
        float w = (k < PP+EE) ? Wih[(size_t)k*G3 + n] : Whh[(size_t)(k-(PP+EE))*G3 + n];
        __nv_bfloat16 hb = __float2bfloat16(w);
        if (hl){
            __nv_bfloat16 lb = __float2bfloat16(w - __bfloat162float(hb));
            q[i2] = *(unsigned short*)&lb;
        } else {
            q[i2] = *(unsigned short*)&hb;
        }
    }
    g_Wf2[id] = make_uint2((q[1]<<16)|q[0], (q[3]<<16)|q[2]);
}

__global__ void k_stop(const float* __restrict__ Ws, const float* __restrict__ bs,
                       float* __restrict__ dout){
    const int w = (blockIdx.x*blockDim.x + threadIdx.x) >> 5;
    const int lane = threadIdx.x & 31;
    if (w >= TT*BB) return;
    const float* hrow = g_Hb + (size_t)w*DD;
    const float* crow = g_Cb + (size_t)w*EE;
    float acc = 0.f;
    for (int k = lane; k < DD; k += 32) acc += hrow[k]*Ws[k];
    for (int k = lane; k < EE; k += 32) acc += crow[k]*Ws[DD+k];
    #pragma unroll
    for (int o = 16; o > 0; o >>= 1) acc += __shfl_down_sync(0xffffffffu, acc, o);
    if (lane == 0){
        const int tq = w / BB, bq = w % BB;
        dout[(size_t)BB*TT*MM + (size_t)bq*TT + tq] = acc + bs[0];
    }
}

// ================= persistent decode kernel =================
__global__ void __launch_bounds__(TPB)
decode(const float* __restrict__ Wd,  const float* __restrict__ bd,
       const float* __restrict__ v,   const float* __restrict__ bv,
       const float* __restrict__ bih, const float* __restrict__ bhh,
       float* __restrict__ out)
{
    extern __shared__ float smf[];
    unsigned* smu = (unsigned*)smf;
    const unsigned sbase = (unsigned)__cvta_generic_to_shared(smf);
    const int blk = blockIdx.x, tid = threadIdx.x;
    const int lane = tid & 31, wq = tid >> 5;
    unsigned gen = g_rel;

    if (blk >= NB){
        // barrier-idler blocks: match real blocks' sync schedule
        for (int t = 0; t < TT; t++){ gsync(gen); psync(gen); gsync(gen); }
        return;
    }

    unsigned attGen = gen;
    const int pair = blk >> 1, ks = blk & 1;
    const uint2* Wsrc = g_Wf2 + (size_t)pair*NCHT*WBLOB;
    const int g = lane >> 2, tig = lane & 3;
    const int nt = wq >> 2;
    const int m0 = (wq & 3) * 16;
    const int c0h = 10 + ks*8;
    const int c0x = ks*5;

    // persistent smem: Wd rows for this block's 8 d's, and v
    for (int r = tid; r < 512; r += TPB)
        ((float4*)(smf + O_WDS))[r] = ((const float4*)(Wd + (size_t)blk*8*AA))[r];
    if (tid < 256) smf[O_VS + tid] = v[tid];
    __syncthreads();

    for (int t = 0; t < TT; t++){
        const int par = t & 1;
        float aX[2][4] = {}, aH[2][4] = {};

        // issue h-part pipeline prologue (stages 0,1) — data ready since last gsync
        if (wq < 12){
            stage_chunk(sbase, 0, 80 + ks*64 + par*128,     Wsrc + (size_t)c0h*WBLOB,     tid);
            stage_chunk(sbase, 1, 80 + ks*64 + par*128 + 8, Wsrc + (size_t)(c0h+1)*WBLOB, tid);
        }

        // ---------- phase 0: dpp reduce (all threads) ----------
        {
            float* part = smf + O_AWS;
            const int a = tid & 255, jh = tid >> 8;
            const float* pp = g_dpp + ((size_t)pair*NB + jh*64)*AA + a;
            float s = 0.f;
            #pragma unroll 16
            for (int j = 0; j < 64; j++) s += pp[(size_t)j*AA];
            part[tid] = s;
            __syncthreads();
            if (tid < 256) smf[O_DPS + tid] = part[tid] + part[256+tid] + bd[tid];
            __syncthreads();
        }
        // ---------- phase 1: scores (all threads) ----------
        {
            const int sl = tid >> 1, ah = tid & 1;
            const int s = ks*256 + sl;
            const uint4* ep4 = (const uint4*)(g_epH + ((size_t)(pair*SS + s))*AA + ah*128);
            const float* dp2 = smf + O_DPS + ah*128;
            const float* v2  = smf + O_VS  + ah*128;
            float acc = 0.f;
            #pragma unroll 4
            for (int q = 0; q < 16; q++){
                uint4 u = ep4[q];
                float2 f0 = __half22float2(*(__half2*)&u.x);
                float2 f1 = __half22float2(*(__half2*)&u.y);
                float2 f2 = __half22float2(*(__half2*)&u.z);
                float2 f3 = __half22float2(*(__half2*)&u.w);
                const int i0 = q*8;
                acc += v2[i0+0]*tanh_mufu(f0.x + dp2[i0+0]);
                acc += v2[i0+1]*tanh_mufu(f0.y + dp2[i0+1]);
                acc += v2[i0+2]*tanh_mufu(f1.x + dp2[i0+2]);
                acc += v2[i0+3]*tanh_mufu(f1.y + dp2[i0+3]);
                acc += v2[i0+4]*tanh_mufu(f2.x + dp2[i0+4]);
                acc += v2[i0+5]*tanh_mufu(f2.y + dp2[i0+5]);
                acc += v2[i0+6]*tanh_mufu(f3.x + dp2[i0+6]);
                acc += v2[i0+7]*tanh_mufu(f3.y + dp2[i0+7]);
            }
            acc += __shfl_xor_sync(0xffffffffu, acc, 1);
            if (ah == 0) g_sc[pair*SS + s] = acc + bv[0];
        }
        __syncthreads();
        // ---------- phase 2: concurrent [h-part MMA (12w) | softmax (4w)] ----------
        if (wq < 12){
            for (int i = 0; i < 8; i++){
                if (i < 6){
                    const int c = c0h + i + 2;
                    stage_chunk(sbase, (i+2)%3, 80 + (c-10)*8 + par*128,
                                Wsrc + (size_t)c*WBLOB, tid);
                } else CP_COMMIT();
                CP_WAIT2();
                BAR2;
                const int slot = i % 3;
                if (nt == 2){ DO_MMA(aH); } else { DO_MMA(aX); }
                BAR2;
            }
        } else {
            const int tl = tid - 384;
            // pair sync: partner's scores visible
            attGen++;
            BAR1;
            if (tl == 0){
                __threadfence();
                g_attf[blk*32] = attGen;
                while (g_attf[(blk^1)*32] < attGen) {}
                __threadfence();
            }
            BAR1;
            float* attr = smf + O_ATTR;
            float4 sc4 = *(const float4*)(g_sc + pair*SS + tl*4);
            float mx = fmaxf(fmaxf(sc4.x, sc4.y), fmaxf(sc4.z, sc4.w));
            #pragma unroll
            for (int o = 16; o; o >>= 1) mx = fmaxf(mx, __shfl_xor_sync(0xffffffffu, mx, o));
            if (lane == 0) attr[wq-12] = mx;
            BAR1;
            mx = fmaxf(fmaxf(attr[0], attr[1]), fmaxf(attr[2], attr[3]));
            float e0 = __expf(sc4.x - mx), e1 = __expf(sc4.y - mx);
            float e2 = __expf(sc4.z - mx), e3 = __expf(sc4.w - mx);
            float ss = e0 + e1 + e2 + e3;
            #pragma unroll
            for (int o = 16; o; o >>= 1) ss += __shfl_xor_sync(0xffffffffu, ss, o);
            if (lane == 0) attr[4 + (wq-12)] = ss;
            BAR1;
            const float inv = __fdividef(1.f, attr[4]+attr[5]+attr[6]+attr[7]);
            float4 av4 = make_float4(e0*inv, e1*inv, e2*inv, e3*inv);
            *(float4*)(smf + O_AWS + tl*4) = av4;
            if (ks == 0){
                *(float4*)(out + (size_t)BB*TT*MM + (size_t)BB*TT + ((size_t)pair*TT + t)*SS + tl*4) = av4;
                float pv = g_pre[((size_t)t*BB + pair)*PP + tl];
                __nv_bfloat16 hb = __float2bfloat16(pv);
                g_Ah[pair*KT2 + tl] = hb;
                g_Al[pair*KT2 + tl] = __float2bfloat16(pv - __bfloat162float(hb));
            }
        }
        __syncthreads();
        // ---------- phase 3: context (all threads; this block's ks half cols) ----------
        {
            const int ec = tid & 63, sq = tid >> 6;   // 8 s-groups x 64 col-quads
            const uint2* eb = (const uint2*)(g_encH + ((size_t)(pair*SS + sq*64))*EE + ks*256 + ec*4);
            const float* awq = smf + O_AWS + sq*64;
            float c0 = 0.f, c1 = 0.f, c2 = 0.f, c3 = 0.f;
            #pragma unroll 8
            for (int s2 = 0; s2 < 64; s2++){
                uint2 u = eb[(size_t)s2*128];
                float a = awq[s2];
                float2 q0 = __half22float2(*(__half2*)&u.x);
                float2 q1 = __half22float2(*(__half2*)&u.y);
                c0 += a*q0.x; c1 += a*q0.y; c2 += a*q1.x; c3 += a*q1.y;
            }
            float* sm2 = smf + O_SM2;
            sm2[sq*256 + ec*4 + 0] = c0;
            sm2[sq*256 + ec*4 + 1] = c1;
            sm2[sq*256 + ec*4 + 2] = c2;
            sm2[sq*256 + ec*4 + 3] = c3;
            __syncthreads();
            if (tid < 256){
                float cc = 0.f;
                #pragma unroll
                for (int q = 0; q < 8; q++) cc += sm2[q*256 + tid];
                const int e2i = ks*256 + tid;
                g_Cb[((size_t)t*BB + pair)*EE + e2i] = cc;
                __nv_bfloat16 hb = __float2bfloat16(cc);
                g_Ah[pair*KT2 + PP + e2i] = hb;
                g_Al[pair*KT2 + PP + e2i] = __float2bfloat16(cc - __bfloat162float(hb));
            }
        }
        gsync(gen);
        // ---------- phase 4: x-part MMA (12w, cp.async 3-stage) ----------
        if (wq < 12){
            stage_chunk(sbase, 0, c0x*8,     Wsrc + (size_t)c0x*WBLOB,     tid);
            stage_chunk(sbase, 1, (c0x+1)*8, Wsrc + (size_t)(c0x+1)*WBLOB, tid);
            for (int i = 0; i < 5; i++){
                if (i < 3){
                    const int c = c0x + i + 2;
                    stage_chunk(sbase, (i+2)%3, c*8, Wsrc + (size_t)c*WBLOB, tid);
                } else CP_COMMIT();
                CP_WAIT2();
                BAR2;
                const int slot = i % 3;
                DO_MMA(aX);
                BAR2;
            }
            // write gate partials [blk][plane][64][16]
            float* gp = g_gp + ((size_t)blk*4 + nt)*1024;
            #pragma unroll
            for (int j = 0; j < 2; j++){
                const int col = j*8 + 2*tig;
                gp[(m0+g)*16 + col]       = aX[j][0];
                gp[(m0+g)*16 + col + 1]   = aX[j][1];
                gp[(m0+g+8)*16 + col]     = aX[j][2];
                gp[(m0+g+8)*16 + col + 1] = aX[j][3];
            }
            if (nt == 2){
                float* gp3 = g_gp + ((size_t)blk*4 + 3)*1024;
                #pragma unroll
                for (int j = 0; j < 2; j++){
                    const int col = j*8 + 2*tig;
                    gp3[(m0+g)*16 + col]       = aH[j][0];
                    gp3[(m0+g)*16 + col + 1]   = aH[j][1];
                    gp3[(m0+g+8)*16 + col]     = aH[j][2];
                    gp3[(m0+g+8)*16 + col + 1] = aH[j][3];
                }
            }
        }
        psync(gen);
        // ---------- phase 5: GRU pointwise + dp k-partials ----------
        {
            float* Wds = smf + O_WDS; float* hs = smf + O_HS;
            {
                const int b = tid >> 3, dl = tid & 7, d = blk*8 + dl;
                const int cd = ks*8 + dl;
                const int o = b*16 + cd;
                const float* gpA = g_gp + (size_t)(pair*2)*4096;
                const float* gpB = gpA + 4096;
                float gr  = gpA[o]        + gpB[o]        + bih[d]      + bhh[d];
                float gz  = gpA[1024 + o] + gpB[1024 + o] + bih[DD+d]   + bhh[DD+d];
                float gin = gpA[2048 + o] + gpB[2048 + o] + bih[2*DD+d];
                float ghn = gpA[3072 + o] + gpB[3072 + o] + bhh[2*DD+d];
                float r = fsig(gr), z = fsig(gz);
                float n = ftanh(gin + r*ghn);
                float h = g_h[b*DD + d];
                float hn = (1.f - z)*n + z*h;
                g_h[b*DD + d] = hn;
                g_Hb[((size_t)t*BB + b)*DD + d] = hn;
                __nv_bfloat16 hb = __float2bfloat16(hn);
                const int hoff = PP+EE + ((t+1)&1)*DD + d;
                g_Ah[b*KT2 + hoff] = hb;
                g_Al[b*KT2 + hoff] = __float2bfloat16(hn - __bfloat162float(hb));
                hs[b*8 + dl] = hn;
            }
            __syncthreads();
            {
                const int bg = tid >> 5, ag = tid & 31;
                const int b4 = bg*4, a8 = ag*8;
                float acc[4][8] = {};
                #pragma unroll
                for (int kk = 0; kk < 8; kk++){
                    const float4 w0 = *(const float4*)(Wds + kk*256 + a8);
                    const float4 w1 = *(const float4*)(Wds + kk*256 + a8 + 4);
                    #pragma unroll
                    for (int i = 0; i < 4; i++){
                        const float h = hs[(b4+i)*8 + kk];
                        acc[i][0]+=h*w0.x; acc[i][1]+=h*w0.y; acc[i][2]+=h*w0.z; acc[i][3]+=h*w0.w;
                        acc[i][4]+=h*w1.x; acc[i][5]+=h*w1.y; acc[i][6]+=h*w1.z; acc[i][7]+=h*w1.w;
                    }
                }
                #pragma unroll
                for (int i = 0; i < 4; i++){
                    float* o = g_dpp + ((size_t)(b4+i)*NB + blk)*AA + a8;
                    *(float4*)(o)   = make_float4(acc[i][0],acc[i][1],acc[i][2],acc[i][3]);
                    *(float4*)(o+4) = make_float4(acc[i][4],acc[i][5],acc[i][6],acc[i][7]);
                }
            }
        }
        gsync(gen);
    }
}

// ---------------- host ----------------
extern "C" void kernel_launch(void* const* d_in, const int* in_sizes, int n_in,
                              void* d_out, int out_size){
    const float* enc = (const float*)d_in[0];
    const float* tm  = (const float*)d_in[1];
    const float* We  = (const float*)d_in[2];
    const float* be  = (const float*)d_in[3];
    const float* Wd  = (const float*)d_in[4];
    const float* bd  = (const float*)d_in[5];
    const float* v   = (const float*)d_in[6];
    const float* bv  = (const float*)d_in[7];
    const float* W1  = (const float*)d_in[8];
    const float* b1  = (const float*)d_in[9];
    const float* W2  = (const float*)d_in[10];
    const float* b2  = (const float*)d_in[11];
    const float* Wih = (const float*)d_in[12];
    const float* bih = (const float*)d_in[13];
    const float* Whh = (const float*)d_in[14];
    const float* bhh = (const float*)d_in[15];
    const float* Wo  = (const float*)d_in[16];
    const float* bo  = (const float*)d_in[17];
    const float* Ws  = (const float*)d_in[18];
    const float* bs  = (const float*)d_in[19];
    float* out = (float*)d_out;

    float *p_prev, *p_ph, *p_pre, *p_Hb, *p_Cb; __half *p_epH;
    cudaGetSymbolAddress((void**)&p_epH,  g_epH);
    cudaGetSymbolAddress((void**)&p_prev, g_prev);
    cudaGetSymbolAddress((void**)&p_ph,   g_ph);
    cudaGetSymbolAddress((void**)&p_pre,  g_pre);
    cudaGetSymbolAddress((void**)&p_Hb,   g_Hb);
    cudaGetSymbolAddress((void**)&p_Cb,   g_Cb);

    cudaFuncSetAttribute(decode, cudaFuncAttributeMaxDynamicSharedMemorySize, SMEM_WORDS*4);

    // precompute
    k_init<<<(BB*NB*AA + 255)/256, 256>>>();
    k_prev<<<(TT*BB*MM + 255)/256, 256>>>(tm);
    k_convE<<<(BB*SS*EE + 255)/256, 256>>>(enc);
    k_pack<<<(64*NCHT*WBLOB + 255)/256, 256>>>(Wih, Whh);
    sgemm<<<dim3(HP/64, (TT*BB)/64), 256>>>(p_prev, W1, b1, p_ph,  TT*BB, HP, MM, 1, 0, 0);
    sgemm<<<dim3(PP/64, (TT*BB)/64), 256>>>(p_ph,   W2, b2, p_pre, TT*BB, PP, HP, 1, 0, 0);
    sgemm<<<dim3(AA/64, (BB*SS)/64), 256>>>(enc,    We, be, (float*)p_epH, BB*SS, AA, EE, 4, 0, 0);

    // sequential decode: one persistent kernel (148 blocks: 128 compute + 20 barrier idlers)
    decode<<<NBL, TPB, SMEM_WORDS*4>>>(Wd, bd, v, bv, bih, bhh, out);

    // output heads
    sgemm<<<dim3(MM/64, (TT*BB)/64), 256>>>(p_Hb, Wo,           bo,      out, TT*BB, MM, DD, 0, BB, TT);
    sgemm<<<dim3(MM/64, (TT*BB)/64), 256>>>(p_Cb, Wo + DD*MM,   nullptr, out, TT*BB, MM, EE, 2, BB, TT);
    k_stop<<<(TT*BB)/8, 256>>>(Ws, bs, out);
}

// round 11
// speedup vs baseline: 2.1464x; 1.2808x over previous
#include <cuda_runtime.h>
#include <cuda_bf16.h>
#include <cuda_fp16.h>

#define BB 64
#define SS 512
#define EE 512
#define AA 256
#define HP 256
#define PP 128
#define DD 1024
#define MM 128
#define TT 800
#define G3 3072
#define NB 128
#define NBL 148
#define TPB 512
#define KT2 2688
#define NCHT 26
#define WBLOB 768          /* uint2 per W chunk blob (fp16 single) */

// dynamic smem layout (float words): 3 slots of (A 2304 + W 1536)
#define SL_A(s) ((s)*3840)
#define SL_W(s) ((s)*3840 + 2304)
#define O_DPS 11520
#define O_VS  11776
#define O_AWS 12032
#define O_ATTR 12544
#define O_SM2 12608
#define O_WDS 14656
#define O_HS  16704
#define SMEM_WORDS 17216

// ---------------- static scratch ----------------
__device__ __align__(128) __half g_epH[BB*SS*AA];
__device__ __align__(128) __half g_encH[BB*SS*EE];
__device__ __align__(128) float g_prev[TT*BB*MM];
__device__ __align__(128) float g_ph  [TT*BB*HP];
__device__ __align__(128) float g_pre [TT*BB*PP];
__device__ __align__(128) float g_h   [BB*DD];
__device__ __align__(128) float g_sc  [BB*SS];
__device__ __align__(128) float g_dpp [BB*NB*AA];
__device__ __align__(128) __half g_Af [BB*KT2];                 // fp16 activations
__device__ __align__(128) uint2 g_Wf2[(size_t)64*NCHT*WBLOB];   // 10.2MB fp16 weights
__device__ __align__(128) float g_gp  [NB*4*64*16];
__device__ __align__(128) float g_Hb  [(size_t)TT*BB*DD];
__device__ __align__(128) float g_Cb  [(size_t)TT*BB*EE];
__device__ __align__(128) volatile unsigned g_flags[NBL*32];
__device__ __align__(128) volatile unsigned g_pairf[NBL*32];
__device__ __align__(128) volatile unsigned g_attf[NB*32];
__device__ volatile unsigned g_rel;

__device__ __forceinline__ float fsig(float x){
    float e = __expf(-x);
    return __fdividef(1.f, 1.f + e);
}
__device__ __forceinline__ float ftanh(float x){
    x = fminf(fmaxf(x, -15.f), 15.f);
    float e = __expf(2.f*x);
    return __fdividef(e - 1.f, e + 1.f);
}
__device__ __forceinline__ float tanh_mufu(float x){
    float y; asm("tanh.approx.f32 %0, %1;" : "=f"(y) : "f"(x)); return y;
}

__device__ __forceinline__ void gsync(unsigned &gen){
    gen++;
    __syncthreads();
    const int tid = threadIdx.x;
    if (blockIdx.x == 0){
        if (tid > 0 && tid < NBL){
            while (g_flags[tid*32] < gen) {}
        }
        __syncthreads();
        if (tid == 0){ __threadfence(); g_rel = gen; }
    } else {
        if (tid == 0){
            __threadfence();
            g_flags[blockIdx.x*32] = gen;
            while (g_rel < gen) {}
            __threadfence();
        }
    }
    __syncthreads();
}

__device__ __forceinline__ void psync(unsigned &gen){
    gen++;
    __syncthreads();
    if (threadIdx.x == 0){
        __threadfence();
        g_pairf[blockIdx.x*32] = gen;
        while (g_pairf[(blockIdx.x^1)*32] < gen) {}
        __threadfence();
    }
    __syncthreads();
}

#define BAR1 asm volatile("bar.sync 1, 128;" ::: "memory")
#define BAR2 asm volatile("bar.sync 2, 384;" ::: "memory")

__device__ __forceinline__ void cp16(unsigned dst, const void* src){
    asm volatile("cp.async.cg.shared.global [%0], [%1], 16;" :: "r"(dst), "l"(src) : "memory");
}
#define CP_COMMIT() asm volatile("cp.async.commit_group;" ::: "memory")
#define CP_WAIT2()  asm volatile("cp.async.wait_group 2;" ::: "memory")

#define MMA(D0,D1,D2,D3,A0,A1,A2,A3,B0,B1) \
    asm volatile("mma.sync.aligned.m16n8k16.row.col.f32.f16.f16.f32 " \
        "{%0,%1,%2,%3},{%4,%5,%6,%7},{%8,%9},{%0,%1,%2,%3};" \
        : "+f"(D0),"+f"(D1),"+f"(D2),"+f"(D3) \
        : "r"(A0),"r"(A1),"r"(A2),"r"(A3),"r"(B0),"r"(B1))

#define DO_MMA(ACC) { \
    const unsigned* A32 = smu + SL_A(slot); \
    const uint2* Wq = (const uint2*)(smu + SL_W(slot)) + nt*256; \
    _Pragma("unroll") \
    for (int kl = 0; kl < 4; kl++){ \
        const int r0 = (m0+g)*36 + kl*8 + tig; \
        unsigned a0 = A32[r0],   a1 = A32[r0+288]; \
        unsigned a2 = A32[r0+4], a3 = A32[r0+292]; \
        _Pragma("unroll") \
        for (int j = 0; j < 2; j++){ \
            uint2 bw = Wq[j*128 + kl*32 + lane]; \
            MMA(ACC[j][0],ACC[j][1],ACC[j][2],ACC[j][3], a0,a1,a2,a3, bw.x,bw.y); \
        } \
    } }

// stage one chunk's A plane (8KB) into slot; called by 384 threads
__device__ __forceinline__ void stage_A(unsigned sbase, int slot, int idx4, int tid){
    #pragma unroll
    for (int k = 0; k < 2; k++){
        int idx = tid + k*384;
        if (idx < 512){
            int row = idx >> 3, col = idx & 7;
            cp16(sbase + (SL_A(slot) + (row*9+col)*4)*4,
                 (const uint4*)g_Af + row*336 + idx4 + col);
        }
    }
}
// stage one chunk's W blob (6KB) into slot; called by 384 threads
__device__ __forceinline__ void stage_W(unsigned sbase, int slot, const uint2* wsrc_c, int tid){
    cp16(sbase + (SL_W(slot))*4 + (unsigned)tid*16, (const uint4*)wsrc_c + tid);
}

// ---------------- generic tiled SGEMM (pre/epilogue only) ----------------
#define BKK 16
__global__ void sgemm(const float* __restrict__ A, const float* __restrict__ B,
                      const float* __restrict__ bias, float* __restrict__ C,
                      int M, int N, int K, int flags, int Bdim, int Tdim)
{
    __shared__ float As[BKK][64];
    __shared__ float Bs[BKK][64];
    const int n0 = blockIdx.x * 64;
    const int m0 = blockIdx.y * 64;
    const int tid = threadIdx.x;
    const int tx = tid & 15;
    const int ty = tid >> 4;
    float acc[4][4] = {};
    const int arow  = tid >> 2;
    const int acol4 = (tid & 3) * 4;
    const int brow  = tid >> 4;
    const int bcol4 = (tid & 15) * 4;

    for (int k = 0; k < K; k += BKK) {
        float4 av = *(const float4*)(A + (size_t)(m0 + arow) * K + k + acol4);
        As[acol4+0][arow] = av.x;
        As[acol4+1][arow] = av.y;
        As[acol4+2][arow] = av.z;
        As[acol4+3][arow] = av.w;
        float4 bvv = *(const float4*)(B + (size_t)(k + brow) * N + n0 + bcol4);
        *(float4*)(&Bs[brow][bcol4]) = bvv;
        __syncthreads();
        #pragma unroll
        for (int kk = 0; kk < BKK; kk++) {
            float4 a4 = *(const float4*)(&As[kk][ty*4]);
            float4 b4 = *(const float4*)(&Bs[kk][tx*4]);
            acc[0][0] += a4.x*b4.x; acc[0][1] += a4.x*b4.y; acc[0][2] += a4.x*b4.z; acc[0][3] += a4.x*b4.w;
            acc[1][0] += a4.y*b4.x; acc[1][1] += a4.y*b4.y; acc[1][2] += a4.y*b4.z; acc[1][3] += a4.y*b4.w;
            acc[2][0] += a4.z*b4.x; acc[2][1] += a4.z*b4.y; acc[2][2] += a4.z*b4.z; acc[2][3] += a4.z*b4.w;
            acc[3][0] += a4.w*b4.x; acc[3][1] += a4.w*b4.y; acc[3][2] += a4.w*b4.z; acc[3][3] += a4.w*b4.w;
        }
        __syncthreads();
    }
    #pragma unroll
    for (int i = 0; i < 4; i++) {
        const int m = m0 + ty*4 + i;
        #pragma unroll
        for (int j = 0; j < 4; j++) {
            const int n = n0 + tx*4 + j;
            float val = acc[i][j];
            if (bias) val += bias[n];
            if (flags & 1) val = fmaxf(val, 0.f);
            size_t idx;
            if (Bdim > 0) {
                const int bq = m % Bdim, tq = m / Bdim;
                idx = ((size_t)bq * Tdim + tq) * N + n;
            } else {
                idx = (size_t)m * N + n;
            }
            if (flags & 4)      ((__half*)C)[idx] = __float2half_rn(val);
            else if (flags & 2) C[idx] += val;
            else                C[idx] = val;
        }
    }
}

__global__ void k_init(){
    int i = blockIdx.x*256 + threadIdx.x;
    if (i < BB*NB*AA) g_dpp[i] = 0.f;
    if (i < BB*KT2) g_Af[i] = __float2half_rn(0.f);
    if (i < BB*DD) g_h[i] = 0.f;
}

__global__ void k_prev(const float* __restrict__ tm){
    int i = blockIdx.x*256 + threadIdx.x;
    if (i >= TT*BB*MM) return;
    int m  = i & (MM-1);
    int tb = i >> 7;
    int b  = tb & (BB-1);
    int t  = tb >> 6;
    g_prev[i] = (t == 0) ? 0.f : tm[((size_t)b*TT + (t-1))*MM + m];
}

__global__ void k_convE(const float* __restrict__ enc){
    int i = blockIdx.x*256 + threadIdx.x;
    if (i < BB*SS*EE) g_encH[i] = __float2half_rn(enc[i]);
}

// pack [Wih; Whh] into per-(pair,chunk) blobs of fp16 mma B-fragments
__global__ void k_pack(const float* __restrict__ Wih, const float* __restrict__ Whh){
    int id = blockIdx.x*256 + threadIdx.x;
    const int TOTW = 64*NCHT*WBLOB;
    if (id >= TOTW) return;
    const int idx2 = id % WBLOB;
    const int lane = idx2 & 31;
    const int kl   = (idx2 >> 5) & 3;
    const int j    = (idx2 >> 7) & 1;
    const int nt   = idx2 >> 8;             // 0..2
    const int c    = (id / WBLOB) % NCHT;
    const int pair = id / (WBLOB*NCHT);
    const int tig = lane & 3;
    const int n = nt*DD + pair*16 + j*8 + (lane >> 2);
    const int k0 = c*64 + kl*16;
    int kk[4] = {k0+2*tig, k0+2*tig+1, k0+8+2*tig, k0+9+2*tig};
    unsigned q[4];
    #pragma unroll
    for (int i2=0;i2<4;i2++){
        int k = kk[i2];
        float w = (k < PP+EE) ? Wih[(size_t)k*G3 + n] : Whh[(size_t)(k-(PP+EE))*G3 + n];
        __half hb = __float2half_rn(w);
        q[i2] = *(unsigned short*)&hb;
    }
    g_Wf2[id] = make_uint2((q[1]<<16)|q[0], (q[3]<<16)|q[2]);
}

__global__ void k_stop(const float* __restrict__ Ws, const float* __restrict__ bs,
                       float* __restrict__ dout){
    const int w = (blockIdx.x*blockDim.x + threadIdx.x) >> 5;
    const int lane = threadIdx.x & 31;
    if (w >= TT*BB) return;
    const float* hrow = g_Hb + (size_t)w*DD;
    const float* crow = g_Cb + (size_t)w*EE;
    float acc = 0.f;
    for (int k = lane; k < DD; k += 32) acc += hrow[k]*Ws[k];
    for (int k = lane; k < EE; k += 32) acc += crow[k]*Ws[DD+k];
    #pragma unroll
    for (int o = 16; o > 0; o >>= 1) acc += __shfl_down_sync(0xffffffffu, acc, o);
    if (lane == 0){
        const int tq = w / BB, bq = w % BB;
        dout[(size_t)BB*TT*MM + (size_t)bq*TT + tq] = acc + bs[0];
    }
}

// ================= persistent decode kernel =================
__global__ void __launch_bounds__(TPB)
decode(const float* __restrict__ Wd,  const float* __restrict__ bd,
       const float* __restrict__ v,   const float* __restrict__ bv,
       const float* __restrict__ bih, const float* __restrict__ bhh,
       float* __restrict__ out)
{
    extern __shared__ float smf[];
    unsigned* smu = (unsigned*)smf;
    const unsigned sbase = (unsigned)__cvta_generic_to_shared(smf);
    const int blk = blockIdx.x, tid = threadIdx.x;
    const int lane = tid & 31, wq = tid >> 5;
    unsigned gen = g_rel;

    if (blk >= NB){
        for (int t = 0; t < TT; t++){ gsync(gen); psync(gen); gsync(gen); }
        return;
    }

    unsigned attGen = gen;
    const int pair = blk >> 1, ks = blk & 1;
    const uint2* Wsrc = g_Wf2 + (size_t)pair*NCHT*WBLOB;
    const int g = lane >> 2, tig = lane & 3;
    const int nt = wq >> 2;
    const int m0 = (wq & 3) * 16;
    const int c0h = 10 + ks*8;
    const int c0x = ks*5;

    // persistent smem: Wd rows for this block's 8 d's, and v
    for (int r = tid; r < 512; r += TPB)
        ((float4*)(smf + O_WDS))[r] = ((const float4*)(Wd + (size_t)blk*8*AA))[r];
    if (tid < 256) smf[O_VS + tid] = v[tid];
    __syncthreads();

    // prologue: prestage W for first 3 h-chunks
    if (wq < 12){
        #pragma unroll
        for (int s = 0; s < 3; s++){
            stage_W(sbase, s, Wsrc + (size_t)(c0h+s)*WBLOB, tid);
            CP_COMMIT();
        }
    }

    for (int t = 0; t < TT; t++){
        const int par = t & 1;
        float aX[2][4] = {}, aH[2][4] = {};

        // h-part A prologue: stage A for h chunks c0h, c0h+1 (data ready post-gsync)
        if (wq < 12){
            stage_A(sbase, 0, 80 + ks*64 + par*128, tid);     CP_COMMIT();
            stage_A(sbase, 1, 80 + ks*64 + par*128 + 8, tid); CP_COMMIT();
        }

        // ---------- phase 0: dpp reduce (all threads) ----------
        {
            float* part = smf + O_AWS;
            const int a = tid & 255, jh = tid >> 8;
            const float* pp = g_dpp + ((size_t)pair*NB + jh*64)*AA + a;
            float s = 0.f;
            #pragma unroll 16
            for (int j = 0; j < 64; j++) s += pp[(size_t)j*AA];
            part[tid] = s;
            __syncthreads();
            if (tid < 256) smf[O_DPS + tid] = part[tid] + part[256+tid] + bd[tid];
            __syncthreads();
        }
        // ---------- phase 1: scores (all threads) ----------
        {
            const int sl = tid >> 1, ah = tid & 1;
            const int s = ks*256 + sl;
            const uint4* ep4 = (const uint4*)(g_epH + ((size_t)(pair*SS + s))*AA + ah*128);
            const float* dp2 = smf + O_DPS + ah*128;
            const float* v2  = smf + O_VS  + ah*128;
            float acc = 0.f;
            #pragma unroll 4
            for (int q = 0; q < 16; q++){
                uint4 u = ep4[q];
                float2 f0 = __half22float2(*(__half2*)&u.x);
                float2 f1 = __half22float2(*(__half2*)&u.y);
                float2 f2 = __half22float2(*(__half2*)&u.z);
                float2 f3 = __half22float2(*(__half2*)&u.w);
                const int i0 = q*8;
                acc += v2[i0+0]*tanh_mufu(f0.x + dp2[i0+0]);
                acc += v2[i0+1]*tanh_mufu(f0.y + dp2[i0+1]);
                acc += v2[i0+2]*tanh_mufu(f1.x + dp2[i0+2]);
                acc += v2[i0+3]*tanh_mufu(f1.y + dp2[i0+3]);
                acc += v2[i0+4]*tanh_mufu(f2.x + dp2[i0+4]);
                acc += v2[i0+5]*tanh_mufu(f2.y + dp2[i0+5]);
                acc += v2[i0+6]*tanh_mufu(f3.x + dp2[i0+6]);
                acc += v2[i0+7]*tanh_mufu(f3.y + dp2[i0+7]);
            }
            acc += __shfl_xor_sync(0xffffffffu, acc, 1);
            if (ah == 0) g_sc[pair*SS + s] = acc + bv[0];
        }
        __syncthreads();
        // ---------- phase 2: concurrent [h-part MMA (12w) | softmax (4w)] ----------
        if (wq < 12){
            for (int i = 0; i < 8; i++){
                if (i < 6){
                    const int c = c0h + i + 2;
                    const int slot2 = (i+2)%3;
                    stage_A(sbase, slot2, 80 + (c-10)*8 + par*128, tid);
                    if (i > 0) stage_W(sbase, slot2, Wsrc + (size_t)c*WBLOB, tid);
                }
                CP_COMMIT();
                CP_WAIT2();
                BAR2;
                const int slot = i % 3;
                if (nt == 2){ DO_MMA(aH); } else { DO_MMA(aX); }
                BAR2;
            }
        } else {
            const int tl = tid - 384;
            attGen++;
            BAR1;
            if (tl == 0){
                __threadfence();
                g_attf[blk*32] = attGen;
                while (g_attf[(blk^1)*32] < attGen) {}
                __threadfence();
            }
            BAR1;
            float* attr = smf + O_ATTR;
            float4 sc4 = *(const float4*)(g_sc + pair*SS + tl*4);
            float mx = fmaxf(fmaxf(sc4.x, sc4.y), fmaxf(sc4.z, sc4.w));
            #pragma unroll
            for (int o = 16; o; o >>= 1) mx = fmaxf(mx, __shfl_xor_sync(0xffffffffu, mx, o));
            if (lane == 0) attr[wq-12] = mx;
            BAR1;
            mx = fmaxf(fmaxf(attr[0], attr[1]), fmaxf(attr[2], attr[3]));
            float e0 = __expf(sc4.x - mx), e1 = __expf(sc4.y - mx);
            float e2 = __expf(sc4.z - mx), e3 = __expf(sc4.w - mx);
            float ss = e0 + e1 + e2 + e3;
            #pragma unroll
            for (int o = 16; o; o >>= 1) ss += __shfl_xor_sync(0xffffffffu, ss, o);
            if (lane == 0) attr[4 + (wq-12)] = ss;
            BAR1;
            const float inv = __fdividef(1.f, attr[4]+attr[5]+attr[6]+attr[7]);
            float4 av4 = make_float4(e0*inv, e1*inv, e2*inv, e3*inv);
            *(float4*)(smf + O_AWS + tl*4) = av4;
            if (ks == 0){
                *(float4*)(out + (size_t)BB*TT*MM + (size_t)BB*TT + ((size_t)pair*TT + t)*SS + tl*4) = av4;
                float pv = g_pre[((size_t)t*BB + pair)*PP + tl];
                g_Af[pair*KT2 + tl] = __float2half_rn(pv);
            }
        }
        __syncthreads();
        // ---------- phase 3: [x-part W prestage] + context (all threads) ----------
        if (wq < 12){
            #pragma unroll
            for (int s = 0; s < 3; s++){
                stage_W(sbase, s, Wsrc + (size_t)(c0x+s)*WBLOB, tid);
                CP_COMMIT();
            }
        }
        {
            const int ec = tid & 63, sq = tid >> 6;
            const uint2* eb = (const uint2*)(g_encH + ((size_t)(pair*SS + sq*64))*EE + ks*256 + ec*4);
            const float* awq = smf + O_AWS + sq*64;
            float c0 = 0.f, c1 = 0.f, c2 = 0.f, c3 = 0.f;
            #pragma unroll 8
            for (int s2 = 0; s2 < 64; s2++){
                uint2 u = eb[(size_t)s2*128];
                float a = awq[s2];
                float2 q0 = __half22float2(*(__half2*)&u.x);
                float2 q1 = __half22float2(*(__half2*)&u.y);
                c0 += a*q0.x; c1 += a*q0.y; c2 += a*q1.x; c3 += a*q1.y;
            }
            float* sm2 = smf + O_SM2;
            sm2[sq*256 + ec*4 + 0] = c0;
            sm2[sq*256 + ec*4 + 1] = c1;
            sm2[sq*256 + ec*4 + 2] = c2;
            sm2[sq*256 + ec*4 + 3] = c3;
            __syncthreads();
            if (tid < 256){
                float cc = 0.f;
                #pragma unroll
                for (int q = 0; q < 8; q++) cc += sm2[q*256 + tid];
                const int e2i = ks*256 + tid;
                g_Cb[((size_t)t*BB + pair)*EE + e2i] = cc;
                g_Af[pair*KT2 + PP + e2i] = __float2half_rn(cc);
            }
        }
        gsync(gen);
        // ---------- phase 4: x-part MMA (12w) ----------
        if (wq < 12){
            stage_A(sbase, 0, c0x*8, tid);     CP_COMMIT();
            stage_A(sbase, 1, (c0x+1)*8, tid); CP_COMMIT();
            for (int i = 0; i < 5; i++){
                if (i < 3){
                    const int c = c0x + i + 2;
                    const int slot2 = (i+2)%3;
                    stage_A(sbase, slot2, c*8, tid);
                    if (i > 0) stage_W(sbase, slot2, Wsrc + (size_t)c*WBLOB, tid);
                }
                CP_COMMIT();
                CP_WAIT2();
                BAR2;
                const int slot = i % 3;
                DO_MMA(aX);
                BAR2;
            }
            // write gate partials [blk][plane][64][16]
            float* gp = g_gp + ((size_t)blk*4 + nt)*1024;
            #pragma unroll
            for (int j = 0; j < 2; j++){
                const int col = j*8 + 2*tig;
                gp[(m0+g)*16 + col]       = aX[j][0];
                gp[(m0+g)*16 + col + 1]   = aX[j][1];
                gp[(m0+g+8)*16 + col]     = aX[j][2];
                gp[(m0+g+8)*16 + col + 1] = aX[j][3];
            }
            if (nt == 2){
                float* gp3 = g_gp + ((size_t)blk*4 + 3)*1024;
                #pragma unroll
                for (int j = 0; j < 2; j++){
                    const int col = j*8 + 2*tig;
                    gp3[(m0+g)*16 + col]       = aH[j][0];
                    gp3[(m0+g)*16 + col + 1]   = aH[j][1];
                    gp3[(m0+g+8)*16 + col]     = aH[j][2];
                    gp3[(m0+g+8)*16 + col + 1] = aH[j][3];
                }
            }
        }
        psync(gen);
        // ---------- phase 5: [next-step h-W prestage] + GRU + dp k-partials ----------
        if (wq < 12){
            #pragma unroll
            for (int s = 0; s < 3; s++){
                stage_W(sbase, s, Wsrc + (size_t)(c0h+s)*WBLOB, tid);
                CP_COMMIT();
            }
        }
        {
            float* Wds = smf + O_WDS; float* hs = smf + O_HS;
            {
                const int b = tid >> 3, dl = tid & 7, d = blk*8 + dl;
                const int cd = ks*8 + dl;
                const int o = b*16 + cd;
                const float* gpA = g_gp + (size_t)(pair*2)*4096;
                const float* gpB = gpA + 4096;
                float gr  = gpA[o]        + gpB[o]        + bih[d]      + bhh[d];
                float gz  = gpA[1024 + o] + gpB[1024 + o] + bih[DD+d]   + bhh[DD+d];
                float gin = gpA[2048 + o] + gpB[2048 + o] + bih[2*DD+d];
                float ghn = gpA[3072 + o] + gpB[3072 + o] + bhh[2*DD+d];
                float r = fsig(gr), z = fsig(gz);
                float n = ftanh(gin + r*ghn);
                float h = g_h[b*DD + d];
                float hn = (1.f - z)*n + z*h;
                g_h[b*DD + d] = hn;
                g_Hb[((size_t)t*BB + b)*DD + d] = hn;
                const int hoff = PP+EE + ((t+1)&1)*DD + d;
                g_Af[b*KT2 + hoff] = __float2half_rn(hn);
                hs[b*8 + dl] = hn;
            }
            __syncthreads();
            {
                const int bg = tid >> 5, ag = tid & 31;
                const int b4 = bg*4, a8 = ag*8;
                float acc[4][8] = {};
                #pragma unroll
                for (int kk = 0; kk < 8; kk++){
                    const float4 w0 = *(const float4*)(Wds + kk*256 + a8);
                    const float4 w1 = *(const float4*)(Wds + kk*256 + a8 + 4);
                    #pragma unroll
                    for (int i = 0; i < 4; i++){
                        const float h = hs[(b4+i)*8 + kk];
                        acc[i][0]+=h*w0.x; acc[i][1]+=h*w0.y; acc[i][2]+=h*w0.z; acc[i][3]+=h*w0.w;
                        acc[i][4]+=h*w1.x; acc[i][5]+=h*w1.y; acc[i][6]+=h*w1.z; acc[i][7]+=h*w1.w;
                    }
                }
                #pragma unroll
                for (int i = 0; i < 4; i++){
                    float* o = g_dpp + ((size_t)(b4+i)*NB + blk)*AA + a8;
                    *(float4*)(o)   = make_float4(acc[i][0],acc[i][1],acc[i][2],acc[i][3]);
                    *(float4*)(o+4) = make_float4(acc[i][4],acc[i][5],acc[i][6],acc[i][7]);
                }
            }
        }
        gsync(gen);
    }
}

// ---------------- host ----------------
extern "C" void kernel_launch(void* const* d_in, const int* in_sizes, int n_in,
                              void* d_out, int out_size){
    const float* enc = (const float*)d_in[0];
    const float* tm  = (const float*)d_in[1];
    const float* We  = (const float*)d_in[2];
    const float* be  = (const float*)d_in[3];
    const float* Wd  = (const float*)d_in[4];
    const float* bd  = (const float*)d_in[5];
    const float* v   = (const float*)d_in[6];
    const float* bv  = (const float*)d_in[7];
    const float* W1  = (const float*)d_in[8];
    const float* b1  = (const float*)d_in[9];
    const float* W2  = (const float*)d_in[10];
    const float* b2  = (const float*)d_in[11];
    const float* Wih = (const float*)d_in[12];
    const float* bih = (const float*)d_in[13];
    const float* Whh = (const float*)d_in[14];
    const float* bhh = (const float*)d_in[15];
    const float* Wo  = (const float*)d_in[16];
    const float* bo  = (const float*)d_in[17];
    const float* Ws  = (const float*)d_in[18];
    const float* bs  = (const float*)d_in[19];
    float* out = (float*)d_out;

    float *p_prev, *p_ph, *p_pre, *p_Hb, *p_Cb; __half *p_epH;
    cudaGetSymbolAddress((void**)&p_epH,  g_epH);
    cudaGetSymbolAddress((void**)&p_prev, g_prev);
    cudaGetSymbolAddress((void**)&p_ph,   g_ph);
    cudaGetSymbolAddress((void**)&p_pre,  g_pre);
    cudaGetSymbolAddress((void**)&p_Hb,   g_Hb);
    cudaGetSymbolAddress((void**)&p_Cb,   g_Cb);

    cudaFuncSetAttribute(decode, cudaFuncAttributeMaxDynamicSharedMemorySize, SMEM_WORDS*4);

    // precompute
    k_init<<<(BB*NB*AA + 255)/256, 256>>>();
    k_prev<<<(TT*BB*MM + 255)/256, 256>>>(tm);
    k_convE<<<(BB*SS*EE + 255)/256, 256>>>(enc);
    k_pack<<<(64*NCHT*WBLOB + 255)/256, 256>>>(Wih, Whh);
    sgemm<<<dim3(HP/64, (TT*BB)/64), 256>>>(p_prev, W1, b1, p_ph,  TT*BB, HP, MM, 1, 0, 0);
    sgemm<<<dim3(PP/64, (TT*BB)/64), 256>>>(p_ph,   W2, b2, p_pre, TT*BB, PP, HP, 1, 0, 0);
    sgemm<<<dim3(AA/64, (BB*SS)/64), 256>>>(enc,    We, be, (float*)p_epH, BB*SS, AA, EE, 4, 0, 0);

    // sequential decode: one persistent kernel
    decode<<<NBL, TPB, SMEM_WORDS*4>>>(Wd, bd, v, bv, bih, bhh, out);

    // output heads
    sgemm<<<dim3(MM/64, (TT*BB)/64), 256>>>(p_Hb, Wo,           bo,      out, TT*BB, MM, DD, 0, BB, TT);
    sgemm<<<dim3(MM/64, (TT*BB)/64), 256>>>(p_Cb, Wo + DD*MM,   nullptr, out, TT*BB, MM, EE, 2, BB, TT);
    k_stop<<<(TT*BB)/8, 256>>>(Ws, bs, out);
}